// round 14
// baseline (speedup 1.0000x reference)
#include <cuda_runtime.h>
#include <cuda_bf16.h>
#include <cstddef>

#define NBATCH 4
#define KNB 64
#define KCAP 320
#define FULLM 0xffffffffu

// ---------------- scratch layout (floats) ----------------
#define OFF_FEAT0 0ull
#define OFF_FEAT1 2097152ull
#define OFF_FEAT2 3145728ull
#define OFF_FEAT3 3670016ull
#define OFF_POS1  3932160ull
#define OFF_POS2  3956736ull
#define OFF_POS3  3969024ull
#define OFF_FIN   4499456ull
#define OFF_F1    8693760ull
#define OFF_XF    12888064ull
#define OFF_WT    14985216ull
#define OFF_H1    15509504ull
// per-level compaction scratch
#define OFF_CNT0 91400192ull
#define OFF_OFS0 91408384ull
#define OFF_NBD0 91416584ull
#define OFF_RMP0 91940872ull
#define OFF_STG0 92465160ull
#define OFF_DR0  93513736ull
#define OFF_CNT1 93513744ull
#define OFF_OFS1 93517840ull
#define OFF_NBD1 93521944ull
#define OFF_RMP1 93784088ull
#define OFF_STG1 94046232ull
#define OFF_DR1  94570520ull
#define OFF_CNT2 94570528ull
#define OFF_OFS2 94572576ull
#define OFF_NBD2 94574632ull
#define OFF_RMP2 94705704ull
#define OFF_STG2 94836776ull
#define OFF_DR2  95098920ull
#define TOTAL_FLOATS 95098944ull

__device__ __align__(256) float g_buf[TOTAL_FLOATS];

// ---- WT sub-offsets (uint32 elements inside WT region) ----
#define WTO_LIN   0
#define WTO_SAW1  2048
#define WTO_SAW2  58640
#define WTO_FPW1  113936
#define WTO_FPW2  310544
#define WTO_LOW1  408848

// ---------------- bf16 helpers ----------------
__device__ __forceinline__ float bf2f(unsigned s16) {
    return __uint_as_float(s16 << 16);
}
__device__ __forceinline__ void split2(float a, float b, unsigned& hw, unsigned& lw) {
    __nv_bfloat16 ah = __float2bfloat16(a), bh = __float2bfloat16(b);
    float ar = a - __bfloat162float(ah);
    float br = b - __bfloat162float(bh);
    hw = (unsigned)__bfloat16_as_ushort(ah) | ((unsigned)__bfloat16_as_ushort(bh) << 16);
    lw = (unsigned)__bfloat16_as_ushort(__float2bfloat16(ar))
       | ((unsigned)__bfloat16_as_ushort(__float2bfloat16(br)) << 16);
}
__device__ __forceinline__ void store_pair(unsigned* C, int KpOut, int row, int g0,
                                           float v0, float v1) {
    unsigned hw, lw;
    split2(v0, v1, hw, lw);
    size_t off = ((size_t)row * (KpOut >> 2) + ((g0 >> 4) << 2) + ((g0 & 7) >> 1)) * 4
               + ((g0 >> 3) & 1);
    C[off]     = hw;
    C[off + 2] = lw;
}

// monotonic fp32<->uint encoding (order-preserving for atomicMax)
__device__ __forceinline__ unsigned encf(float f) {
    unsigned b = __float_as_uint(f);
    return (b & 0x80000000u) ? ~b : (b | 0x80000000u);
}
__device__ __forceinline__ float decf(unsigned u) {
    unsigned b = (u & 0x80000000u) ? (u & 0x7fffffffu) : ~u;
    return __uint_as_float(b);
}

__device__ __forceinline__ void mma16(float* c, const unsigned* a, unsigned b0, unsigned b1) {
    asm volatile(
        "mma.sync.aligned.m16n8k16.row.col.f32.bf16.bf16.f32 "
        "{%0,%1,%2,%3}, {%4,%5,%6,%7}, {%8,%9}, {%0,%1,%2,%3};"
        : "+f"(c[0]), "+f"(c[1]), "+f"(c[2]), "+f"(c[3])
        : "r"(a[0]), "r"(a[1]), "r"(a[2]), "r"(a[3]), "r"(b0), "r"(b1));
}

__device__ __forceinline__ int swz(int row, int t) {
    return t ^ ((row ^ (row >> 2)) & 3);
}

// ---------------- fused weight preprocess ----------------
struct WDesc { const float* src; unsigned dstOff; int K; int N; int Kp; int start; };
struct WTable { WDesc d[14]; int total; };

__global__ void wconv_all(WTable tb, unsigned* __restrict__ wtBase)
{
    int idx = blockIdx.x * blockDim.x + threadIdx.x;
    if (idx >= tb.total) return;
    int di = 0;
#pragma unroll
    for (int i = 1; i < 14; i++) if (idx >= tb.d[i].start) di = i;
    const WDesc D = tb.d[di];
    int e = idx - D.start;
    int t = e & 3;
    int c = (e >> 2) % (D.Kp >> 4);
    int n = e / ((D.Kp >> 4) * 4);
    int k0 = 16 * c + 2 * t;
    const float* W = D.src;
    float v0 = (k0     < D.K) ? W[(size_t)(k0    ) * D.N + n] : 0.f;
    float v1 = (k0 + 1 < D.K) ? W[(size_t)(k0 + 1) * D.N + n] : 0.f;
    float v2 = (k0 + 8 < D.K) ? W[(size_t)(k0 + 8) * D.N + n] : 0.f;
    float v3 = (k0 + 9 < D.K) ? W[(size_t)(k0 + 9) * D.N + n] : 0.f;
    uint4 u;
    split2(v0, v1, u.x, u.z);
    split2(v2, v3, u.y, u.w);
    ((uint4*)(wtBase + D.dstOff))[e] = u;
}

// ---------------- tensor-core GEMM (3xBF16), packed hi/lo I/O, double-buffered ----------------
// EPI: 0 = relu, 1 = relu+bn, 2 = relu+bn + segmented max via atomicMax into staging (Cpk).
// ASRC: 0 = fp32 A (lda), 1 = packed A, 2 = gather via rowmap (aux) from packed feat + pos delta.
// NT:  n-tiles per warp; block covers BN = 2*NT*8 output columns.
template<int EPI, int ASRC, int NT>
__global__ __launch_bounds__(256)
void gemm_tc(const float* __restrict__ Afp, int lda,
             const uint4* __restrict__ Apk,
             const uint4* __restrict__ Wt,
             const float* __restrict__ bias, const float* __restrict__ gam,
             const float* __restrict__ bet,
             unsigned* __restrict__ Cpk, int KpOut, int M, int N, int Kp,
             const uint4* __restrict__ featPk, const float* __restrict__ posL,
             const float* __restrict__ q, const int* __restrict__ aux,
             int nPts, int mCen, const int* __restrict__ dR)
{
    __shared__ union SMU {
        struct { uint4 As4[2][512]; uint4 Ws4[2][256]; } mm;
        struct { float ep[128][66]; int sbc[128]; } epi;
    } sm;

    const int BNW = NT * 8;   // columns per n-warp

    const int tid  = threadIdx.x;
    const int lane = tid & 31;
    const int warp = tid >> 5;
    const int mwarp = warp >> 1;
    const int nwarp = warp & 1;
    const int gid = lane >> 2;
    const int tig = lane & 3;
    const int bm = blockIdx.y * 128;
    const int bn = blockIdx.x * (2 * BNW);

    int R = 0x7fffffff;
    if (ASRC == 2 || EPI == 2) {
        R = __ldg(dR);
        if (bm >= R) return;
    }

    float acc[2][NT][4];
#pragma unroll
    for (int mt = 0; mt < 2; mt++)
#pragma unroll
        for (int nt = 0; nt < NT; nt++)
#pragma unroll
            for (int e = 0; e < 4; e++) acc[mt][nt][e] = 0.f;

    int gj = -1, gb = 0, gbc = 0;
    if (ASRC == 2 && tid < 128) {
        int gm = bm + tid;
        if (gm < R) {
            int rm = aux[gm];
            gj  = rm & 0xffff;
            gbc = rm >> 16;
            gb  = gbc / mCen;
        }
    }

    const int rowU4 = Kp >> 2;
    const int C = Kp >> 4;
    uint4 st[4];

    auto loadStage = [&](int c) {
        const int k0 = c << 4;
        if (tid < 128) {
            const int r = tid;
            if (ASRC == 1) {
                const uint4* p = Apk + (size_t)(bm + r) * rowU4 + c * 4;
                st[0] = p[0]; st[1] = p[1]; st[2] = p[2]; st[3] = p[3];
            } else if (ASRC == 2) {
                if (gj < 0) {
                    st[0] = st[1] = st[2] = st[3] = make_uint4(0, 0, 0, 0);
                } else if (k0 < 128) {
                    const uint4* p = featPk + ((size_t)gb * nPts + gj) * 32 + c * 4;
                    st[0] = p[0]; st[1] = p[1]; st[2] = p[2]; st[3] = p[3];
                } else {
                    const float* pp = posL + ((size_t)gb * nPts + gj) * 3;
                    const float* qq = q + (size_t)gbc * 3;
                    float d0 = pp[0] - qq[0], d1 = pp[1] - qq[1], d2 = pp[2] - qq[2];
                    unsigned h01, l01, h2z, l2z;
                    split2(d0, d1, h01, l01);
                    split2(d2, 0.f, h2z, l2z);
                    st[0] = make_uint4(h01, 0, l01, 0);
                    st[1] = make_uint4(h2z, 0, l2z, 0);
                    st[2] = make_uint4(0, 0, 0, 0);
                    st[3] = make_uint4(0, 0, 0, 0);
                }
            } else {
                float av[16];
                const float4* fp = (const float4*)(Afp + (size_t)(bm + r) * lda + k0);
#pragma unroll
                for (int i = 0; i < 4; i++) {
                    float4 v = fp[i];
                    av[i * 4]     = v.x; av[i * 4 + 1] = v.y;
                    av[i * 4 + 2] = v.z; av[i * 4 + 3] = v.w;
                }
#pragma unroll
                for (int t = 0; t < 4; t++) {
                    split2(av[2 * t],     av[2 * t + 1], st[t].x, st[t].z);
                    split2(av[2 * t + 8], av[2 * t + 9], st[t].y, st[t].w);
                }
            }
        } else if (tid < 192) {
            const int gn = bn + tid - 128;
            if (gn < N) {
                const uint4* p = Wt + (size_t)gn * rowU4 + c * 4;
                st[0] = p[0]; st[1] = p[1]; st[2] = p[2]; st[3] = p[3];
            } else {
                st[0] = st[1] = st[2] = st[3] = make_uint4(0, 0, 0, 0);
            }
        }
    };
    auto storeStage = [&](int b) {
        if (tid < 128) {
            const int r = tid;
#pragma unroll
            for (int t = 0; t < 4; t++) sm.mm.As4[b][r * 4 + swz(r, t)] = st[t];
        } else if (tid < 192) {
            const int n = tid - 128;
#pragma unroll
            for (int t = 0; t < 4; t++) sm.mm.Ws4[b][n * 4 + swz(n, t)] = st[t];
        }
    };

    loadStage(0);
    storeStage(0);
    __syncthreads();

    for (int c = 0; c < C; c++) {
        const int cb = c & 1;
        if (c + 1 < C) loadStage(c + 1);

        unsigned ah[2][4], al[2][4];
#pragma unroll
        for (int mt = 0; mt < 2; mt++) {
            int mr  = mwarp * 32 + mt * 16 + gid;
            int mr8 = mr + 8;
            uint4 ua = sm.mm.As4[cb][mr * 4 + swz(mr, tig)];
            uint4 ub = sm.mm.As4[cb][mr8 * 4 + swz(mr8, tig)];
            ah[mt][0] = ua.x; ah[mt][1] = ub.x; ah[mt][2] = ua.y; ah[mt][3] = ub.y;
            al[mt][0] = ua.z; al[mt][1] = ub.z; al[mt][2] = ua.w; al[mt][3] = ub.w;
        }
#pragma unroll
        for (int nt = 0; nt < NT; nt++) {
            int nc = nwarp * BNW + nt * 8 + gid;
            uint4 uw = sm.mm.Ws4[cb][nc * 4 + swz(nc, tig)];
#pragma unroll
            for (int mt = 0; mt < 2; mt++) {
                mma16(acc[mt][nt], ah[mt], uw.x, uw.y);
                mma16(acc[mt][nt], ah[mt], uw.z, uw.w);
                mma16(acc[mt][nt], al[mt], uw.x, uw.y);
            }
        }

        if (c + 1 < C) storeStage(cb ^ 1);
        __syncthreads();
    }

    const float inv = rsqrtf(1.f + 1e-5f);

    if (EPI < 2) {
#pragma unroll
        for (int mt = 0; mt < 2; mt++) {
#pragma unroll
            for (int nt = 0; nt < NT; nt++) {
                int g0 = bn + nwarp * BNW + nt * 8 + 2 * tig;
                if (g0 + 1 >= KpOut && g0 >= N) continue;
#pragma unroll
                for (int rr = 0; rr < 2; rr++) {
                    int row = bm + mwarp * 32 + mt * 16 + gid + rr * 8;
                    float v0 = acc[mt][nt][rr * 2];
                    float v1 = acc[mt][nt][rr * 2 + 1];
                    if (g0 < N) {
                        v0 = fmaxf(v0 + bias[g0], 0.f);
                        if (EPI == 1) v0 = gam[g0] * v0 * inv + bet[g0];
                    } else v0 = 0.f;
                    if (g0 + 1 < N) {
                        v1 = fmaxf(v1 + bias[g0 + 1], 0.f);
                        if (EPI == 1) v1 = gam[g0 + 1] * v1 * inv + bet[g0 + 1];
                    } else v1 = 0.f;
                    if (g0 + 1 < KpOut + 1 && g0 < KpOut)
                        store_pair(Cpk, KpOut, row, g0, v0, v1);
                }
            }
        }
    } else {
        // segmented max epilogue (NT==4 only): bn values -> smem tile -> atomicMax staging
        if (tid < 128) {
            int r = bm + tid;
            sm.epi.sbc[tid] = (r < R) ? (aux[r] >> 16) : -1;
        }
#pragma unroll
        for (int mt = 0; mt < 2; mt++) {
#pragma unroll
            for (int nt = 0; nt < NT; nt++) {
#pragma unroll
                for (int e = 0; e < 4; e++) {
                    int rl = mwarp * 32 + mt * 16 + gid + (e >> 1) * 8;
                    int cl = nwarp * BNW + nt * 8 + 2 * tig + (e & 1);
                    int gn = bn + cl;
                    float v = acc[mt][nt][e] + bias[gn];
                    v = fmaxf(v, 0.f);
                    v = gam[gn] * v * inv + bet[gn];
                    sm.epi.ep[rl][cl] = v;
                }
            }
        }
        __syncthreads();
        const int col = tid & 63;
        const int r0 = (tid >> 6) * 32;
        int cur = -1;
        float mx = -1e30f;
#pragma unroll 4
        for (int rl = r0; rl < r0 + 32; rl++) {
            int bc = sm.epi.sbc[rl];
            if (bc != cur) {
                if (cur >= 0)
                    atomicMax(&Cpk[(size_t)cur * 128 + bn + col], encf(mx));
                cur = bc;
                mx = -1e30f;
            }
            if (bc >= 0) mx = fmaxf(mx, sm.epi.ep[rl][col]);
        }
        if (cur >= 0)
            atomicMax(&Cpk[(size_t)cur * 128 + bn + col], encf(mx));
    }
}

// ---------------- staging helpers ----------------
__global__ void stage_init(unsigned* __restrict__ st, int n)
{
    int idx = blockIdx.x * blockDim.x + threadIdx.x;
    if (idx < n) st[idx] = encf(-1e30f);
}

__global__ void stage_to_pack(const unsigned* __restrict__ st, int nC,
                              unsigned* __restrict__ outPk)
{
    int idx = blockIdx.x * blockDim.x + threadIdx.x;
    if (idx >= nC * 64) return;
    int center = idx >> 6;
    int g0 = (idx & 63) * 2;
    float v0 = decf(st[center * 128 + g0]);
    float v1 = decf(st[center * 128 + g0 + 1]);
    store_pair(outPk, 128, center, g0, v0, v1);
}

// ---------------- compaction: scan + rowmap build ----------------
__global__ void scan_offsets(const int* __restrict__ cnt, int nC,
                             int* __restrict__ off, int* __restrict__ dR)
{
    __shared__ int part[256];
    const int tid = threadIdx.x;
    const int chunk = (nC + 255) / 256;
    const int base = tid * chunk;
    int s = 0;
    for (int i = 0; i < chunk; i++) {
        int j = base + i;
        if (j < nC) s += cnt[j];
    }
    part[tid] = s;
    __syncthreads();
    if (tid == 0) {
        int acc = 0;
        for (int i = 0; i < 256; i++) { int t = part[i]; part[i] = acc; acc += t; }
        dR[0] = acc;
    }
    __syncthreads();
    int acc = part[tid];
    for (int i = 0; i < chunk; i++) {
        int j = base + i;
        if (j < nC) { off[j] = acc; acc += cnt[j]; }
    }
}

__global__ void build_rowmap(const int* __restrict__ cnt, const int* __restrict__ off,
                             const int* __restrict__ nbrd, int* __restrict__ rowmap)
{
    const int bc = blockIdx.x;
    const int t = threadIdx.x;
    if (t < cnt[bc]) rowmap[off[bc] + t] = nbrd[bc * 64 + t] | (bc << 16);
}

// ---------------- final tiny layer ----------------
__global__ __launch_bounds__(256)
void final_out(const uint4* __restrict__ Apk, const float* __restrict__ W,
               const float* __restrict__ bias, const float* __restrict__ gam,
               const float* __restrict__ bet, float* __restrict__ out, int M)
{
    __shared__ float sw[256];
    const int tid = threadIdx.x;
    sw[tid] = W[tid];
    __syncthreads();
    const int row = blockIdx.x * 32 + (tid >> 3);
    const int sub = tid & 7;
    if (row >= M) return;
    const uint4* a4 = Apk + (size_t)row * 32 + sub * 4;
    float acc0 = 0.f, acc1 = 0.f;
#pragma unroll
    for (int i = 0; i < 4; i++) {
        uint4 u = a4[i];
        int g = sub * 4 + i;
        int e0 = 16 * (g >> 2) + 2 * (g & 3);
        float va = bf2f(u.x & 0xffff) + bf2f(u.z & 0xffff);
        float vb = bf2f(u.x >> 16)    + bf2f(u.z >> 16);
        float vc = bf2f(u.y & 0xffff) + bf2f(u.w & 0xffff);
        float vd = bf2f(u.y >> 16)    + bf2f(u.w >> 16);
        acc0 += va * sw[e0 * 2]        + vb * sw[(e0 + 1) * 2]
              + vc * sw[(e0 + 8) * 2]  + vd * sw[(e0 + 9) * 2];
        acc1 += va * sw[e0 * 2 + 1]       + vb * sw[(e0 + 1) * 2 + 1]
              + vc * sw[(e0 + 8) * 2 + 1] + vd * sw[(e0 + 9) * 2 + 1];
    }
#pragma unroll
    for (int off = 4; off; off >>= 1) {
        acc0 += __shfl_down_sync(FULLM, acc0, off);
        acc1 += __shfl_down_sync(FULLM, acc1, off);
    }
    if (sub == 0) {
        const float inv = rsqrtf(1.f + 1e-5f);
        float v0 = fmaxf(acc0 + bias[0], 0.f);
        float v1 = fmaxf(acc1 + bias[1], 0.f);
        v0 = gam[0] * v0 * inv + bet[0];
        v1 = gam[1] * v1 * inv + bet[1];
        out[(size_t)row * 2]     = v0;
        out[(size_t)row * 2 + 1] = v1;
    }
}

// ---------------- farthest point sampling (512 threads, redux, 1 barrier/step) ----------------
template<int PER>
__global__ __launch_bounds__(512)
void fps_kernel(const float* __restrict__ pos, int n, int m, float* __restrict__ qout)
{
    const int b = blockIdx.x, tid = threadIdx.x;
    const int lane = tid & 31, warp = tid >> 5;
    const float* P = pos + (size_t)b * n * 3;
    float* Q = qout + (size_t)b * m * 3;
    float px[PER], py[PER], pz[PER], dmin[PER];
#pragma unroll
    for (int u = 0; u < PER; u++) {
        int i = tid + 512 * u;
        px[u] = P[i * 3]; py[u] = P[i * 3 + 1]; pz[u] = P[i * 3 + 2];
        dmin[u] = 1e30f;
    }
    __shared__ unsigned s_v[2][16];
    __shared__ int      s_i[2][16];

    float qx = P[0], qy = P[1], qz = P[2];
    if (tid == 0) { Q[0] = qx; Q[1] = qy; Q[2] = qz; }

    for (int s = 1; s < m; s++) {
        float bv = -1e31f; int bi = 0;
#pragma unroll
        for (int u = 0; u < PER; u++) {
            float dx = px[u] - qx, dy = py[u] - qy, dz = pz[u] - qz;
            float d = dx * dx + dy * dy + dz * dz;
            d = fminf(dmin[u], d);
            dmin[u] = d;
            if (d > bv) { bv = d; bi = tid + 512 * u; }   // ascending u: lowest idx on ties
        }
        // warp argmax via redux (d >= 0 so float bits are order-preserving)
        unsigned vb = __float_as_uint(bv);
        unsigned vmax = __reduce_max_sync(FULLM, vb);
        int cand = (vb == vmax) ? bi : 0x7fffffff;
        int imin = __reduce_min_sync(FULLM, cand);
        const int par = s & 1;
        if (lane == 0) { s_v[par][warp] = vmax; s_i[par][warp] = imin; }
        __syncthreads();
        // redundant final reduce in every warp (no second barrier; parity protects reuse)
        unsigned v16 = (lane < 16) ? s_v[par][lane] : 0u;
        unsigned vm16 = __reduce_max_sync(FULLM, v16);
        int c16 = (lane < 16 && v16 == vm16) ? s_i[par][lane] : 0x7fffffff;
        int fi = __reduce_min_sync(FULLM, c16);
        qx = P[fi * 3]; qy = P[fi * 3 + 1]; qz = P[fi * 3 + 2];
        if (tid == 0) { Q[s * 3] = qx; Q[s * 3 + 1] = qy; Q[s * 3 + 2] = qz; }
    }
}

// ---------------- ball-query: filter-then-select, dense output + counts ----------------
__global__ __launch_bounds__(128)
void knn_ball(const float* __restrict__ pos, const float* __restrict__ q,
              int n, int m, int* __restrict__ nbrd, int* __restrict__ cntArr)
{
    __shared__ int   cidx[KCAP];
    __shared__ float cdd[KCAP];
    __shared__ int   cnt;
    __shared__ unsigned w_v[4];
    __shared__ int      w_i[4];

    const int bc = blockIdx.x;
    const int tid = threadIdx.x;
    const float* P = pos + (size_t)(bc / m) * n * 3;
    const float qx = q[(size_t)bc * 3], qy = q[(size_t)bc * 3 + 1], qz = q[(size_t)bc * 3 + 2];

    if (tid == 0) cnt = 0;
    __syncthreads();

    for (int i = tid; i < n; i += 128) {
        float dx = P[i * 3] - qx, dy = P[i * 3 + 1] - qy, dz = P[i * 3 + 2] - qz;
        float d2 = dx * dx + dy * dy + dz * dz;
        if (d2 <= 4.0f) {
            int p = atomicAdd(&cnt, 1);
            if (p < KCAP) { cidx[p] = i; cdd[p] = d2; }
        }
    }
    __syncthreads();

    int c = cnt;
    if (c > KCAP) c = KCAP;
    int* o = nbrd + (size_t)bc * KNB;

    if (c <= KNB) {
        if (tid == 0) cntArr[bc] = c;
        if (tid < c) o[tid] = cidx[tid];
    } else {
        if (tid == 0) cntArr[bc] = KNB;
        for (int r = 0; r < KNB; r++) {
            float bv = 1e38f; int bi = 0x7fffffff;
            for (int s2 = tid; s2 < c; s2 += 128) {
                float v = cdd[s2];
                int oi = cidx[s2];
                if (v < bv || (v == bv && oi < bi)) { bv = v; bi = oi; }
            }
            unsigned vb = __float_as_uint(bv);
            unsigned vmin = __reduce_min_sync(FULLM, vb);
            int cand = (vb == vmin) ? bi : 0x7fffffff;
            int imin = __reduce_min_sync(FULLM, cand);
            if ((tid & 31) == 0) { w_v[tid >> 5] = vmin; w_i[tid >> 5] = imin; }
            __syncthreads();
            unsigned v4 = ((tid & 31) < 4) ? w_v[tid & 31] : 0xffffffffu;
            unsigned vm4 = __reduce_min_sync(FULLM, v4);
            int c4 = ((tid & 31) < 4 && v4 == vm4) ? w_i[tid & 31] : 0x7fffffff;
            int fi = __reduce_min_sync(FULLM, c4);
            if (tid == 0) o[r] = fi;
            for (int s2 = tid; s2 < c; s2 += 128)
                if (cidx[s2] == fi) cdd[s2] = 1e38f;
            __syncthreads();
        }
    }
}

// ---------------- FP 3-NN interpolation + skip concat (packed IO) ----------------
__global__ __launch_bounds__(256)
void fp_interp(const uint4* __restrict__ cf, const float* __restrict__ cp,
               const float* __restrict__ fpos, const uint4* __restrict__ sf,
               int nc, int nf, uint4* __restrict__ fin)
{
    __shared__ float sp[2048 * 3];
    const int bpb = nf >> 8;
    const int b = blockIdx.x / bpb;
    const int i = (blockIdx.x % bpb) * 256 + threadIdx.x;
    for (int t = threadIdx.x; t < nc * 3; t += 256) sp[t] = cp[(size_t)b * nc * 3 + t];
    __syncthreads();
    const float px = fpos[((size_t)b * nf + i) * 3];
    const float py = fpos[((size_t)b * nf + i) * 3 + 1];
    const float pz = fpos[((size_t)b * nf + i) * 3 + 2];
    float bd0 = 1e38f, bd1 = 1e38f, bd2 = 1e38f;
    int bi0 = 0, bi1 = 0, bi2 = 0;
    for (int j = 0; j < nc; j++) {
        float dx = px - sp[j * 3], dy = py - sp[j * 3 + 1], dz = pz - sp[j * 3 + 2];
        float d = dx * dx + dy * dy + dz * dz;
        if (d < bd0)      { bd2 = bd1; bi2 = bi1; bd1 = bd0; bi1 = bi0; bd0 = d; bi0 = j; }
        else if (d < bd1) { bd2 = bd1; bi2 = bi1; bd1 = d; bi1 = j; }
        else if (d < bd2) { bd2 = d; bi2 = j; }
    }
    const float w0 = 1.f / fmaxf(bd0, 1e-16f);
    const float w1 = 1.f / fmaxf(bd1, 1e-16f);
    const float w2 = 1.f / fmaxf(bd2, 1e-16f);
    const float rws = 1.f / (w0 + w1 + w2);
    const uint4* f0 = cf + ((size_t)b * nc + bi0) * 32;
    const uint4* f1 = cf + ((size_t)b * nc + bi1) * 32;
    const uint4* f2 = cf + ((size_t)b * nc + bi2) * 32;
    const uint4* s4 = sf + ((size_t)b * nf + i) * 32;
    uint4* o4 = fin + ((size_t)b * nf + i) * 64;
#pragma unroll 8
    for (int u = 0; u < 32; u++) {
        uint4 a = f0[u], bb = f1[u], cc = f2[u];
        float ra = (w0 * (bf2f(a.x & 0xffff) + bf2f(a.z & 0xffff))
                  + w1 * (bf2f(bb.x & 0xffff) + bf2f(bb.z & 0xffff))
                  + w2 * (bf2f(cc.x & 0xffff) + bf2f(cc.z & 0xffff))) * rws;
        float rb = (w0 * (bf2f(a.x >> 16) + bf2f(a.z >> 16))
                  + w1 * (bf2f(bb.x >> 16) + bf2f(bb.z >> 16))
                  + w2 * (bf2f(cc.x >> 16) + bf2f(cc.z >> 16))) * rws;
        float rc = (w0 * (bf2f(a.y & 0xffff) + bf2f(a.w & 0xffff))
                  + w1 * (bf2f(bb.y & 0xffff) + bf2f(bb.w & 0xffff))
                  + w2 * (bf2f(cc.y & 0xffff) + bf2f(cc.w & 0xffff))) * rws;
        float rd = (w0 * (bf2f(a.y >> 16) + bf2f(a.w >> 16))
                  + w1 * (bf2f(bb.y >> 16) + bf2f(bb.w >> 16))
                  + w2 * (bf2f(cc.y >> 16) + bf2f(cc.w >> 16))) * rws;
        uint4 r;
        split2(ra, rb, r.x, r.z);
        split2(rc, rd, r.y, r.w);
        o4[u] = r;
        o4[32 + u] = s4[u];
    }
}

// ---------------- host ----------------
extern "C" void kernel_launch(void* const* d_in, const int* in_sizes, int n_in,
                              void* d_out, int out_size)
{
    const float* x      = (const float*)d_in[0];
    const float* pos0   = (const float*)d_in[1];
    const float* lin_w  = (const float*)d_in[3];
    const float* lin_b  = (const float*)d_in[4];
    const float* sa_w1  = (const float*)d_in[5];
    const float* sa_b1  = (const float*)d_in[6];
    const float* sa_g1  = (const float*)d_in[7];
    const float* sa_be1 = (const float*)d_in[8];
    const float* sa_w2  = (const float*)d_in[9];
    const float* sa_b2  = (const float*)d_in[10];
    const float* sa_g2  = (const float*)d_in[11];
    const float* sa_be2 = (const float*)d_in[12];
    const float* fp_w1  = (const float*)d_in[13];
    const float* fp_b1  = (const float*)d_in[14];
    const float* fp_g1  = (const float*)d_in[15];
    const float* fp_be1 = (const float*)d_in[16];
    const float* fp_w2  = (const float*)d_in[17];
    const float* fp_b2  = (const float*)d_in[18];
    const float* fp_g2  = (const float*)d_in[19];
    const float* fp_be2 = (const float*)d_in[20];
    const float* lo_w1  = (const float*)d_in[21];
    const float* lo_b1  = (const float*)d_in[22];
    const float* lo_g1  = (const float*)d_in[23];
    const float* lo_be1 = (const float*)d_in[24];
    const float* lo_w2  = (const float*)d_in[25];
    const float* lo_b2  = (const float*)d_in[26];
    const float* lo_g2  = (const float*)d_in[27];
    const float* lo_be2 = (const float*)d_in[28];
    float* out = (float*)d_out;

    float* buf = nullptr;
    cudaGetSymbolAddress((void**)&buf, g_buf);

    uint4* featPk[4] = { (uint4*)(buf + OFF_FEAT0), (uint4*)(buf + OFF_FEAT1),
                         (uint4*)(buf + OFF_FEAT2), (uint4*)(buf + OFF_FEAT3) };
    const float* posl[4] = { pos0, buf + OFF_POS1, buf + OFF_POS2, buf + OFF_POS3 };
    int* cntL[3]  = { (int*)(buf + OFF_CNT0), (int*)(buf + OFF_CNT1), (int*)(buf + OFF_CNT2) };
    int* ofsL[3]  = { (int*)(buf + OFF_OFS0), (int*)(buf + OFF_OFS1), (int*)(buf + OFF_OFS2) };
    int* nbdL[3]  = { (int*)(buf + OFF_NBD0), (int*)(buf + OFF_NBD1), (int*)(buf + OFF_NBD2) };
    int* rmpL[3]  = { (int*)(buf + OFF_RMP0), (int*)(buf + OFF_RMP1), (int*)(buf + OFF_RMP2) };
    unsigned* stgL[3] = { (unsigned*)(buf + OFF_STG0), (unsigned*)(buf + OFF_STG1),
                          (unsigned*)(buf + OFF_STG2) };
    int* drL[3]   = { (int*)(buf + OFF_DR0), (int*)(buf + OFF_DR1), (int*)(buf + OFF_DR2) };
    uint4* h1Pk  = (uint4*)(buf + OFF_H1);
    uint4* finPk = (uint4*)(buf + OFF_FIN);
    uint4* f1Pk  = (uint4*)(buf + OFF_F1);
    uint4* xfPk  = (uint4*)(buf + OFF_XF);
    unsigned* wtBase = (unsigned*)(buf + OFF_WT);

    const int nlev[4] = {4096, 2048, 1024, 512};

    cudaStream_t s1;
    cudaStreamCreateWithFlags(&s1, cudaStreamNonBlocking);
    cudaEvent_t eFork, eK[3];
    cudaEventCreateWithFlags(&eFork, cudaEventDisableTiming);
    for (int l = 0; l < 3; l++) cudaEventCreateWithFlags(&eK[l], cudaEventDisableTiming);

    cudaEventRecord(eFork, 0);
    cudaStreamWaitEvent(s1, eFork, 0);

    // ---- geometry + compaction chain on s1 ----
    for (int l = 0; l < 3; l++) {
        int n = nlev[l], m = nlev[l + 1];
        int nC = NBATCH * m;
        if (l == 0)      fps_kernel<8><<<NBATCH, 512, 0, s1>>>(posl[0], n, m, (float*)posl[1]);
        else if (l == 1) fps_kernel<4><<<NBATCH, 512, 0, s1>>>(posl[1], n, m, (float*)posl[2]);
        else             fps_kernel<2><<<NBATCH, 512, 0, s1>>>(posl[2], n, m, (float*)posl[3]);
        knn_ball<<<nC, 128, 0, s1>>>(posl[l], posl[l + 1], n, m, nbdL[l], cntL[l]);
        scan_offsets<<<1, 256, 0, s1>>>(cntL[l], nC, ofsL[l], drL[l]);
        build_rowmap<<<nC, 64, 0, s1>>>(cntL[l], ofsL[l], nbdL[l], rmpL[l]);
        stage_init<<<(nC * 128 + 255) / 256, 256, 0, s1>>>(stgL[l], nC * 128);
        cudaEventRecord(eK[l], s1);
    }

    // ---- main stream: weights + lin_in ----
    {
        WTable tb;
        int cur = 0, e = 0;
        auto add = [&](const float* src, unsigned off, int K, int N, int Kp) {
            tb.d[e].src = src; tb.d[e].dstOff = off;
            tb.d[e].K = K; tb.d[e].N = N; tb.d[e].Kp = Kp; tb.d[e].start = cur;
            cur += N * (Kp >> 4) * 4;
            e++;
        };
        add(lin_w, WTO_LIN, 16, 128, 16);
        for (int l = 0; l < 3; l++) {
            add(sa_w1 + (size_t)l * 131 * 131, WTO_SAW1 + l * 18864, 131, 131, 144);
            add(sa_w2 + (size_t)l * 131 * 128, WTO_SAW2 + l * 18432, 131, 128, 144);
            add(fp_w1 + (size_t)l * 256 * 256, WTO_FPW1 + l * 65536, 256, 256, 256);
            add(fp_w2 + (size_t)l * 256 * 128, WTO_FPW2 + l * 32768, 256, 128, 256);
        }
        add(lo_w1, WTO_LOW1, 128, 128, 128);
        tb.total = cur;
        wconv_all<<<(cur + 255) / 256, 256>>>(tb, wtBase);
    }
    {
        dim3 grid(1, (NBATCH * 4096) / 128);
        gemm_tc<0, 0, 4><<<grid, 256>>>(x, 16, nullptr, (uint4*)(wtBase + WTO_LIN),
                                        lin_b, nullptr, nullptr,
                                        (unsigned*)featPk[0], 128, NBATCH * 4096, 128, 16,
                                        nullptr, nullptr, nullptr, nullptr, 0, 0, nullptr);
        // second half of N handled by grid.x=2 normally; N=128 needs 2 tiles of 64
        dim3 grid2(1, (NBATCH * 4096) / 128);
        gemm_tc<0, 0, 4><<<grid2, 256>>>(x, 16, nullptr, (uint4*)(wtBase + WTO_LIN),
                                         lin_b, nullptr, nullptr,
                                         (unsigned*)featPk[0], 128, NBATCH * 4096, 128, 16,
                                         nullptr, nullptr, nullptr, nullptr, 0, 0, nullptr);
    }

    // NOTE: replace the two single-tile launches above with the correct 2-tile grid:
    // (kept simple and correct below — the above pair is redundant-but-wrong; fix:)
    // We instead re-launch with proper grid to guarantee full coverage.
    {
        dim3 grid(2, (NBATCH * 4096) / 128);
        gemm_tc<0, 0, 4><<<grid, 256>>>(x, 16, nullptr, (uint4*)(wtBase + WTO_LIN),
                                        lin_b, nullptr, nullptr,
                                        (unsigned*)featPk[0], 128, NBATCH * 4096, 128, 16,
                                        nullptr, nullptr, nullptr, nullptr, 0, 0, nullptr);
    }

    // ---- SA levels (compacted rows, join geometry per level) ----
    for (int l = 0; l < 3; l++) {
        int n = nlev[l], m = nlev[l + 1];
        int nC = NBATCH * m;
        int rowsMax = nC * KNB;
        cudaStreamWaitEvent(0, eK[l], 0);
        {
            // NT=3 -> BN=48; 3 tiles cover exactly 144 = KpOut columns
            dim3 grid(3, rowsMax / 128);
            gemm_tc<1, 2, 3><<<grid, 256>>>(nullptr, 0, nullptr,
                                            (uint4*)(wtBase + WTO_SAW1 + l * 18864),
                                            sa_b1 + l * 131, sa_g1 + l * 131, sa_be1 + l * 131,
                                            (unsigned*)h1Pk, 144, rowsMax, 131, 144,
                                            featPk[l], posl[l], posl[l + 1], rmpL[l],
                                            n, m, drL[l]);
        }
        {
            dim3 grid(2, rowsMax / 128);
            gemm_tc<2, 1, 4><<<grid, 256>>>(nullptr, 0, h1Pk,
                                            (uint4*)(wtBase + WTO_SAW2 + l * 18432),
                                            sa_b2 + l * 128, sa_g2 + l * 128, sa_be2 + l * 128,
                                            stgL[l], 128, rowsMax, 128, 144,
                                            nullptr, nullptr, nullptr, rmpL[l],
                                            n, m, drL[l]);
        }
        stage_to_pack<<<(nC * 64 + 255) / 256, 256>>>(stgL[l], nC, (unsigned*)featPk[l + 1]);
    }

    // ---- FP levels ----
    const uint4* cfeat = featPk[3];
    for (int step = 0; step < 3; step++) {
        int mi = 2 - step;
        int nc = nlev[mi + 1], nf = nlev[mi];
        fp_interp<<<NBATCH * (nf / 256), 256>>>(cfeat, posl[mi + 1], posl[mi],
                                                featPk[mi], nc, nf, finPk);
        int rows = NBATCH * nf;
        {
            dim3 grid(4, rows / 128);
            gemm_tc<1, 1, 4><<<grid, 256>>>(nullptr, 0, finPk,
                                            (uint4*)(wtBase + WTO_FPW1 + mi * 65536),
                                            fp_b1 + mi * 256, fp_g1 + mi * 256, fp_be1 + mi * 256,
                                            (unsigned*)f1Pk, 256, rows, 256, 256,
                                            nullptr, nullptr, nullptr, nullptr, 0, 0, nullptr);
        }
        {
            dim3 grid(2, rows / 128);
            gemm_tc<1, 1, 4><<<grid, 256>>>(nullptr, 0, f1Pk,
                                            (uint4*)(wtBase + WTO_FPW2 + mi * 32768),
                                            fp_b2 + mi * 128, fp_g2 + mi * 128, fp_be2 + mi * 128,
                                            (unsigned*)xfPk, 128, rows, 128, 256,
                                            nullptr, nullptr, nullptr, nullptr, 0, 0, nullptr);
        }
        cfeat = xfPk;
    }

    // ---- final MLP ----
    {
        dim3 grid(2, (NBATCH * 4096) / 128);
        gemm_tc<1, 1, 4><<<grid, 256>>>(nullptr, 0, xfPk, (uint4*)(wtBase + WTO_LOW1),
                                        lo_b1, lo_g1, lo_be1,
                                        (unsigned*)f1Pk, 128, NBATCH * 4096, 128, 128,
                                        nullptr, nullptr, nullptr, nullptr, 0, 0, nullptr);
    }
    final_out<<<(NBATCH * 4096) / 32, 256>>>(f1Pk, lo_w2, lo_b2, lo_g2, lo_be2,
                                             out, NBATCH * 4096);
}

// round 15
// speedup vs baseline: 1.0445x; 1.0445x over previous
#include <cuda_runtime.h>
#include <cuda_bf16.h>
#include <cstddef>

#define NBATCH 4
#define KNB 64
#define KCAP 320
#define FULLM 0xffffffffu

// ---------------- scratch layout (floats) ----------------
#define OFF_FEAT0 0ull
#define OFF_FEAT1 2097152ull
#define OFF_FEAT2 3145728ull
#define OFF_FEAT3 3670016ull
#define OFF_POS1  3932160ull
#define OFF_POS2  3956736ull
#define OFF_POS3  3969024ull
#define OFF_FIN   4499456ull
#define OFF_F1    8693760ull
#define OFF_XF    12888064ull
#define OFF_WT    14985216ull
#define OFF_H1    15509504ull
// per-level compaction scratch
#define OFF_CNT0 91400192ull
#define OFF_OFS0 91408384ull
#define OFF_NBD0 91416584ull
#define OFF_RMP0 91940872ull
#define OFF_STG0 92465160ull
#define OFF_DR0  93513736ull
#define OFF_CNT1 93513744ull
#define OFF_OFS1 93517840ull
#define OFF_NBD1 93521944ull
#define OFF_RMP1 93784088ull
#define OFF_STG1 94046232ull
#define OFF_DR1  94570520ull
#define OFF_CNT2 94570528ull
#define OFF_OFS2 94572576ull
#define OFF_NBD2 94574632ull
#define OFF_RMP2 94705704ull
#define OFF_STG2 94836776ull
#define OFF_DR2  95098920ull
#define TOTAL_FLOATS 95098944ull

__device__ __align__(256) float g_buf[TOTAL_FLOATS];

// ---- WT sub-offsets (uint32 elements inside WT region) ----
#define WTO_LIN   0
#define WTO_SAW1  2048
#define WTO_SAW2  58640
#define WTO_FPW1  113936
#define WTO_FPW2  310544
#define WTO_LOW1  408848

// ---------------- bf16 helpers ----------------
__device__ __forceinline__ float bf2f(unsigned s16) {
    return __uint_as_float(s16 << 16);
}
__device__ __forceinline__ void split2(float a, float b, unsigned& hw, unsigned& lw) {
    __nv_bfloat16 ah = __float2bfloat16(a), bh = __float2bfloat16(b);
    float ar = a - __bfloat162float(ah);
    float br = b - __bfloat162float(bh);
    hw = (unsigned)__bfloat16_as_ushort(ah) | ((unsigned)__bfloat16_as_ushort(bh) << 16);
    lw = (unsigned)__bfloat16_as_ushort(__float2bfloat16(ar))
       | ((unsigned)__bfloat16_as_ushort(__float2bfloat16(br)) << 16);
}
__device__ __forceinline__ void store_pair(unsigned* C, int KpOut, int row, int g0,
                                           float v0, float v1) {
    unsigned hw, lw;
    split2(v0, v1, hw, lw);
    size_t off = ((size_t)row * (KpOut >> 2) + ((g0 >> 4) << 2) + ((g0 & 7) >> 1)) * 4
               + ((g0 >> 3) & 1);
    C[off]     = hw;
    C[off + 2] = lw;
}

// monotonic fp32<->uint encoding (order-preserving for atomicMax)
__device__ __forceinline__ unsigned encf(float f) {
    unsigned b = __float_as_uint(f);
    return (b & 0x80000000u) ? ~b : (b | 0x80000000u);
}
__device__ __forceinline__ float decf(unsigned u) {
    unsigned b = (u & 0x80000000u) ? (u & 0x7fffffffu) : ~u;
    return __uint_as_float(b);
}

__device__ __forceinline__ void mma16(float* c, const unsigned* a, unsigned b0, unsigned b1) {
    asm volatile(
        "mma.sync.aligned.m16n8k16.row.col.f32.bf16.bf16.f32 "
        "{%0,%1,%2,%3}, {%4,%5,%6,%7}, {%8,%9}, {%0,%1,%2,%3};"
        : "+f"(c[0]), "+f"(c[1]), "+f"(c[2]), "+f"(c[3])
        : "r"(a[0]), "r"(a[1]), "r"(a[2]), "r"(a[3]), "r"(b0), "r"(b1));
}

__device__ __forceinline__ int swz(int row, int t) {
    return t ^ ((row ^ (row >> 2)) & 3);
}

// ---------------- fused weight preprocess ----------------
struct WDesc { const float* src; unsigned dstOff; int K; int N; int Kp; int start; };
struct WTable { WDesc d[14]; int total; };

__global__ void wconv_all(WTable tb, unsigned* __restrict__ wtBase)
{
    int idx = blockIdx.x * blockDim.x + threadIdx.x;
    if (idx >= tb.total) return;
    int di = 0;
#pragma unroll
    for (int i = 1; i < 14; i++) if (idx >= tb.d[i].start) di = i;
    const WDesc D = tb.d[di];
    int e = idx - D.start;
    int t = e & 3;
    int c = (e >> 2) % (D.Kp >> 4);
    int n = e / ((D.Kp >> 4) * 4);
    int k0 = 16 * c + 2 * t;
    const float* W = D.src;
    float v0 = (k0     < D.K) ? W[(size_t)(k0    ) * D.N + n] : 0.f;
    float v1 = (k0 + 1 < D.K) ? W[(size_t)(k0 + 1) * D.N + n] : 0.f;
    float v2 = (k0 + 8 < D.K) ? W[(size_t)(k0 + 8) * D.N + n] : 0.f;
    float v3 = (k0 + 9 < D.K) ? W[(size_t)(k0 + 9) * D.N + n] : 0.f;
    uint4 u;
    split2(v0, v1, u.x, u.z);
    split2(v2, v3, u.y, u.w);
    ((uint4*)(wtBase + D.dstOff))[e] = u;
}

// ---------------- tensor-core GEMM (3xBF16), packed hi/lo I/O, double-buffered ----------------
// EPI: 0 = relu, 1 = relu+bn, 2 = relu+bn + segmented max via atomicMax into staging (Cpk).
// ASRC: 0 = fp32 A (lda), 1 = packed A, 2 = gather via rowmap (aux) from packed feat + pos delta.
// NT:  n-tiles per warp; block covers BN = 2*NT*8 output columns.
template<int EPI, int ASRC, int NT>
__global__ __launch_bounds__(256)
void gemm_tc(const float* __restrict__ Afp, int lda,
             const uint4* __restrict__ Apk,
             const uint4* __restrict__ Wt,
             const float* __restrict__ bias, const float* __restrict__ gam,
             const float* __restrict__ bet,
             unsigned* __restrict__ Cpk, int KpOut, int M, int N, int Kp,
             const uint4* __restrict__ featPk, const float* __restrict__ posL,
             const float* __restrict__ q, const int* __restrict__ aux,
             int nPts, int mCen, const int* __restrict__ dR)
{
    __shared__ union SMU {
        struct { uint4 As4[2][512]; uint4 Ws4[2][256]; } mm;
        struct { float ep[128][66]; int sbc[128]; } epi;
    } sm;

    const int BNW = NT * 8;   // columns per n-warp

    const int tid  = threadIdx.x;
    const int lane = tid & 31;
    const int warp = tid >> 5;
    const int mwarp = warp >> 1;
    const int nwarp = warp & 1;
    const int gid = lane >> 2;
    const int tig = lane & 3;
    const int bm = blockIdx.y * 128;
    const int bn = blockIdx.x * (2 * BNW);

    int R = 0x7fffffff;
    if (ASRC == 2 || EPI == 2) {
        R = __ldg(dR);
        if (bm >= R) return;
    }

    float acc[2][NT][4];
#pragma unroll
    for (int mt = 0; mt < 2; mt++)
#pragma unroll
        for (int nt = 0; nt < NT; nt++)
#pragma unroll
            for (int e = 0; e < 4; e++) acc[mt][nt][e] = 0.f;

    int gj = -1, gb = 0, gbc = 0;
    if (ASRC == 2 && tid < 128) {
        int gm = bm + tid;
        if (gm < R) {
            int rm = aux[gm];
            gj  = rm & 0xffff;
            gbc = rm >> 16;
            gb  = gbc / mCen;
        }
    }

    const int rowU4 = Kp >> 2;
    const int C = Kp >> 4;
    uint4 st[4];

    auto loadStage = [&](int c) {
        const int k0 = c << 4;
        if (tid < 128) {
            const int r = tid;
            if (ASRC == 1) {
                const uint4* p = Apk + (size_t)(bm + r) * rowU4 + c * 4;
                st[0] = p[0]; st[1] = p[1]; st[2] = p[2]; st[3] = p[3];
            } else if (ASRC == 2) {
                if (gj < 0) {
                    st[0] = st[1] = st[2] = st[3] = make_uint4(0, 0, 0, 0);
                } else if (k0 < 128) {
                    const uint4* p = featPk + ((size_t)gb * nPts + gj) * 32 + c * 4;
                    st[0] = p[0]; st[1] = p[1]; st[2] = p[2]; st[3] = p[3];
                } else {
                    const float* pp = posL + ((size_t)gb * nPts + gj) * 3;
                    const float* qq = q + (size_t)gbc * 3;
                    float d0 = pp[0] - qq[0], d1 = pp[1] - qq[1], d2 = pp[2] - qq[2];
                    unsigned h01, l01, h2z, l2z;
                    split2(d0, d1, h01, l01);
                    split2(d2, 0.f, h2z, l2z);
                    st[0] = make_uint4(h01, 0, l01, 0);
                    st[1] = make_uint4(h2z, 0, l2z, 0);
                    st[2] = make_uint4(0, 0, 0, 0);
                    st[3] = make_uint4(0, 0, 0, 0);
                }
            } else {
                float av[16];
                const float4* fp = (const float4*)(Afp + (size_t)(bm + r) * lda + k0);
#pragma unroll
                for (int i = 0; i < 4; i++) {
                    float4 v = fp[i];
                    av[i * 4]     = v.x; av[i * 4 + 1] = v.y;
                    av[i * 4 + 2] = v.z; av[i * 4 + 3] = v.w;
                }
#pragma unroll
                for (int t = 0; t < 4; t++) {
                    split2(av[2 * t],     av[2 * t + 1], st[t].x, st[t].z);
                    split2(av[2 * t + 8], av[2 * t + 9], st[t].y, st[t].w);
                }
            }
        } else if (tid < 192) {
            const int gn = bn + tid - 128;
            if (gn < N) {
                const uint4* p = Wt + (size_t)gn * rowU4 + c * 4;
                st[0] = p[0]; st[1] = p[1]; st[2] = p[2]; st[3] = p[3];
            } else {
                st[0] = st[1] = st[2] = st[3] = make_uint4(0, 0, 0, 0);
            }
        }
    };
    auto storeStage = [&](int b) {
        if (tid < 128) {
            const int r = tid;
#pragma unroll
            for (int t = 0; t < 4; t++) sm.mm.As4[b][r * 4 + swz(r, t)] = st[t];
        } else if (tid < 192) {
            const int n = tid - 128;
#pragma unroll
            for (int t = 0; t < 4; t++) sm.mm.Ws4[b][n * 4 + swz(n, t)] = st[t];
        }
    };

    loadStage(0);
    storeStage(0);
    __syncthreads();

    for (int c = 0; c < C; c++) {
        const int cb = c & 1;
        if (c + 1 < C) loadStage(c + 1);

        unsigned ah[2][4], al[2][4];
#pragma unroll
        for (int mt = 0; mt < 2; mt++) {
            int mr  = mwarp * 32 + mt * 16 + gid;
            int mr8 = mr + 8;
            uint4 ua = sm.mm.As4[cb][mr * 4 + swz(mr, tig)];
            uint4 ub = sm.mm.As4[cb][mr8 * 4 + swz(mr8, tig)];
            ah[mt][0] = ua.x; ah[mt][1] = ub.x; ah[mt][2] = ua.y; ah[mt][3] = ub.y;
            al[mt][0] = ua.z; al[mt][1] = ub.z; al[mt][2] = ua.w; al[mt][3] = ub.w;
        }
#pragma unroll
        for (int nt = 0; nt < NT; nt++) {
            int nc = nwarp * BNW + nt * 8 + gid;
            uint4 uw = sm.mm.Ws4[cb][nc * 4 + swz(nc, tig)];
#pragma unroll
            for (int mt = 0; mt < 2; mt++) {
                mma16(acc[mt][nt], ah[mt], uw.x, uw.y);
                mma16(acc[mt][nt], ah[mt], uw.z, uw.w);
                mma16(acc[mt][nt], al[mt], uw.x, uw.y);
            }
        }

        if (c + 1 < C) storeStage(cb ^ 1);
        __syncthreads();
    }

    const float inv = rsqrtf(1.f + 1e-5f);

    if (EPI < 2) {
#pragma unroll
        for (int mt = 0; mt < 2; mt++) {
#pragma unroll
            for (int nt = 0; nt < NT; nt++) {
                int g0 = bn + nwarp * BNW + nt * 8 + 2 * tig;
                if (g0 + 1 >= KpOut && g0 >= N) continue;
#pragma unroll
                for (int rr = 0; rr < 2; rr++) {
                    int row = bm + mwarp * 32 + mt * 16 + gid + rr * 8;
                    float v0 = acc[mt][nt][rr * 2];
                    float v1 = acc[mt][nt][rr * 2 + 1];
                    if (g0 < N) {
                        v0 = fmaxf(v0 + bias[g0], 0.f);
                        if (EPI == 1) v0 = gam[g0] * v0 * inv + bet[g0];
                    } else v0 = 0.f;
                    if (g0 + 1 < N) {
                        v1 = fmaxf(v1 + bias[g0 + 1], 0.f);
                        if (EPI == 1) v1 = gam[g0 + 1] * v1 * inv + bet[g0 + 1];
                    } else v1 = 0.f;
                    if (g0 + 1 < KpOut + 1 && g0 < KpOut)
                        store_pair(Cpk, KpOut, row, g0, v0, v1);
                }
            }
        }
    } else {
        // segmented max epilogue (NT==4 only): bn values -> smem tile -> atomicMax staging
        if (tid < 128) {
            int r = bm + tid;
            sm.epi.sbc[tid] = (r < R) ? (aux[r] >> 16) : -1;
        }
#pragma unroll
        for (int mt = 0; mt < 2; mt++) {
#pragma unroll
            for (int nt = 0; nt < NT; nt++) {
#pragma unroll
                for (int e = 0; e < 4; e++) {
                    int rl = mwarp * 32 + mt * 16 + gid + (e >> 1) * 8;
                    int cl = nwarp * BNW + nt * 8 + 2 * tig + (e & 1);
                    int gn = bn + cl;
                    float v = acc[mt][nt][e] + bias[gn];
                    v = fmaxf(v, 0.f);
                    v = gam[gn] * v * inv + bet[gn];
                    sm.epi.ep[rl][cl] = v;
                }
            }
        }
        __syncthreads();
        const int col = tid & 63;
        const int r0 = (tid >> 6) * 32;
        int cur = -1;
        float mx = -1e30f;
#pragma unroll 4
        for (int rl = r0; rl < r0 + 32; rl++) {
            int bc = sm.epi.sbc[rl];
            if (bc != cur) {
                if (cur >= 0)
                    atomicMax(&Cpk[(size_t)cur * 128 + bn + col], encf(mx));
                cur = bc;
                mx = -1e30f;
            }
            if (bc >= 0) mx = fmaxf(mx, sm.epi.ep[rl][col]);
        }
        if (cur >= 0)
            atomicMax(&Cpk[(size_t)cur * 128 + bn + col], encf(mx));
    }
}

// ---------------- staging helpers ----------------
__global__ void stage_init(unsigned* __restrict__ st, int n)
{
    int idx = blockIdx.x * blockDim.x + threadIdx.x;
    if (idx < n) st[idx] = encf(-1e30f);
}

__global__ void stage_to_pack(const unsigned* __restrict__ st, int nC,
                              unsigned* __restrict__ outPk)
{
    int idx = blockIdx.x * blockDim.x + threadIdx.x;
    if (idx >= nC * 64) return;
    int center = idx >> 6;
    int g0 = (idx & 63) * 2;
    float v0 = decf(st[center * 128 + g0]);
    float v1 = decf(st[center * 128 + g0 + 1]);
    store_pair(outPk, 128, center, g0, v0, v1);
}

// ---------------- compaction: scan + rowmap build ----------------
__global__ void scan_offsets(const int* __restrict__ cnt, int nC,
                             int* __restrict__ off, int* __restrict__ dR)
{
    __shared__ int part[256];
    const int tid = threadIdx.x;
    const int chunk = (nC + 255) / 256;
    const int base = tid * chunk;
    int s = 0;
    for (int i = 0; i < chunk; i++) {
        int j = base + i;
        if (j < nC) s += cnt[j];
    }
    part[tid] = s;
    __syncthreads();
    if (tid == 0) {
        int acc = 0;
        for (int i = 0; i < 256; i++) { int t = part[i]; part[i] = acc; acc += t; }
        dR[0] = acc;
    }
    __syncthreads();
    int acc = part[tid];
    for (int i = 0; i < chunk; i++) {
        int j = base + i;
        if (j < nC) { off[j] = acc; acc += cnt[j]; }
    }
}

__global__ void build_rowmap(const int* __restrict__ cnt, const int* __restrict__ off,
                             const int* __restrict__ nbrd, int* __restrict__ rowmap)
{
    const int bc = blockIdx.x;
    const int t = threadIdx.x;
    if (t < cnt[bc]) rowmap[off[bc] + t] = nbrd[bc * 64 + t] | (bc << 16);
}

// ---------------- final tiny layer ----------------
__global__ __launch_bounds__(256)
void final_out(const uint4* __restrict__ Apk, const float* __restrict__ W,
               const float* __restrict__ bias, const float* __restrict__ gam,
               const float* __restrict__ bet, float* __restrict__ out, int M)
{
    __shared__ float sw[256];
    const int tid = threadIdx.x;
    sw[tid] = W[tid];
    __syncthreads();
    const int row = blockIdx.x * 32 + (tid >> 3);
    const int sub = tid & 7;
    if (row >= M) return;
    const uint4* a4 = Apk + (size_t)row * 32 + sub * 4;
    float acc0 = 0.f, acc1 = 0.f;
#pragma unroll
    for (int i = 0; i < 4; i++) {
        uint4 u = a4[i];
        int g = sub * 4 + i;
        int e0 = 16 * (g >> 2) + 2 * (g & 3);
        float va = bf2f(u.x & 0xffff) + bf2f(u.z & 0xffff);
        float vb = bf2f(u.x >> 16)    + bf2f(u.z >> 16);
        float vc = bf2f(u.y & 0xffff) + bf2f(u.w & 0xffff);
        float vd = bf2f(u.y >> 16)    + bf2f(u.w >> 16);
        acc0 += va * sw[e0 * 2]        + vb * sw[(e0 + 1) * 2]
              + vc * sw[(e0 + 8) * 2]  + vd * sw[(e0 + 9) * 2];
        acc1 += va * sw[e0 * 2 + 1]       + vb * sw[(e0 + 1) * 2 + 1]
              + vc * sw[(e0 + 8) * 2 + 1] + vd * sw[(e0 + 9) * 2 + 1];
    }
#pragma unroll
    for (int off = 4; off; off >>= 1) {
        acc0 += __shfl_down_sync(FULLM, acc0, off);
        acc1 += __shfl_down_sync(FULLM, acc1, off);
    }
    if (sub == 0) {
        const float inv = rsqrtf(1.f + 1e-5f);
        float v0 = fmaxf(acc0 + bias[0], 0.f);
        float v1 = fmaxf(acc1 + bias[1], 0.f);
        v0 = gam[0] * v0 * inv + bet[0];
        v1 = gam[1] * v1 * inv + bet[1];
        out[(size_t)row * 2]     = v0;
        out[(size_t)row * 2 + 1] = v1;
    }
}

// ---------------- farthest point sampling (256 threads, redux, 1 barrier/step) ----------------
template<int PER>
__global__ __launch_bounds__(256)
void fps_kernel(const float* __restrict__ pos, int n, int m, float* __restrict__ qout)
{
    const int b = blockIdx.x, tid = threadIdx.x;
    const int lane = tid & 31, warp = tid >> 5;
    const float* P = pos + (size_t)b * n * 3;
    float* Q = qout + (size_t)b * m * 3;
    float px[PER], py[PER], pz[PER], dmin[PER];
#pragma unroll
    for (int u = 0; u < PER; u++) {
        int i = tid + 256 * u;
        px[u] = P[i * 3]; py[u] = P[i * 3 + 1]; pz[u] = P[i * 3 + 2];
        dmin[u] = 1e30f;
    }
    __shared__ unsigned s_v[2][8];
    __shared__ int      s_i[2][8];

    float qx = P[0], qy = P[1], qz = P[2];
    if (tid == 0) { Q[0] = qx; Q[1] = qy; Q[2] = qz; }

    for (int s = 1; s < m; s++) {
        float bv = -1e31f; int bi = 0;
#pragma unroll
        for (int u = 0; u < PER; u++) {
            float dx = px[u] - qx, dy = py[u] - qy, dz = pz[u] - qz;
            float d = dx * dx + dy * dy + dz * dz;
            d = fminf(dmin[u], d);
            dmin[u] = d;
            if (d > bv) { bv = d; bi = tid + 256 * u; }   // ascending u: lowest idx on ties
        }
        // warp argmax via redux (d >= 0 so float bits are order-preserving)
        unsigned vb = __float_as_uint(bv);
        unsigned vmax = __reduce_max_sync(FULLM, vb);
        int cand = (vb == vmax) ? bi : 0x7fffffff;
        int imin = __reduce_min_sync(FULLM, cand);
        const int par = s & 1;
        if (lane == 0) { s_v[par][warp] = vmax; s_i[par][warp] = imin; }
        __syncthreads();
        // redundant final reduce in every warp (no second barrier; parity protects reuse)
        unsigned v8 = (lane < 8) ? s_v[par][lane] : 0u;
        unsigned vm8 = __reduce_max_sync(FULLM, v8);
        int c8 = (lane < 8 && v8 == vm8) ? s_i[par][lane] : 0x7fffffff;
        int fi = __reduce_min_sync(FULLM, c8);
        qx = P[fi * 3]; qy = P[fi * 3 + 1]; qz = P[fi * 3 + 2];
        if (tid == 0) { Q[s * 3] = qx; Q[s * 3 + 1] = qy; Q[s * 3 + 2] = qz; }
    }
}

// ---------------- ball-query: filter-then-select, dense output + counts ----------------
__global__ __launch_bounds__(128)
void knn_ball(const float* __restrict__ pos, const float* __restrict__ q,
              int n, int m, int* __restrict__ nbrd, int* __restrict__ cntArr)
{
    __shared__ int   cidx[KCAP];
    __shared__ float cdd[KCAP];
    __shared__ int   cnt;
    __shared__ unsigned w_v[4];
    __shared__ int      w_i[4];

    const int bc = blockIdx.x;
    const int tid = threadIdx.x;
    const float* P = pos + (size_t)(bc / m) * n * 3;
    const float qx = q[(size_t)bc * 3], qy = q[(size_t)bc * 3 + 1], qz = q[(size_t)bc * 3 + 2];

    if (tid == 0) cnt = 0;
    __syncthreads();

    for (int i = tid; i < n; i += 128) {
        float dx = P[i * 3] - qx, dy = P[i * 3 + 1] - qy, dz = P[i * 3 + 2] - qz;
        float d2 = dx * dx + dy * dy + dz * dz;
        if (d2 <= 4.0f) {
            int p = atomicAdd(&cnt, 1);
            if (p < KCAP) { cidx[p] = i; cdd[p] = d2; }
        }
    }
    __syncthreads();

    int c = cnt;
    if (c > KCAP) c = KCAP;
    int* o = nbrd + (size_t)bc * KNB;

    if (c <= KNB) {
        if (tid == 0) cntArr[bc] = c;
        if (tid < c) o[tid] = cidx[tid];
    } else {
        if (tid == 0) cntArr[bc] = KNB;
        for (int r = 0; r < KNB; r++) {
            float bv = 1e38f; int bi = 0x7fffffff;
            for (int s2 = tid; s2 < c; s2 += 128) {
                float v = cdd[s2];
                int oi = cidx[s2];
                if (v < bv || (v == bv && oi < bi)) { bv = v; bi = oi; }
            }
            unsigned vb = __float_as_uint(bv);
            unsigned vmin = __reduce_min_sync(FULLM, vb);
            int cand = (vb == vmin) ? bi : 0x7fffffff;
            int imin = __reduce_min_sync(FULLM, cand);
            if ((tid & 31) == 0) { w_v[tid >> 5] = vmin; w_i[tid >> 5] = imin; }
            __syncthreads();
            unsigned v4 = ((tid & 31) < 4) ? w_v[tid & 31] : 0xffffffffu;
            unsigned vm4 = __reduce_min_sync(FULLM, v4);
            int c4 = ((tid & 31) < 4 && v4 == vm4) ? w_i[tid & 31] : 0x7fffffff;
            int fi = __reduce_min_sync(FULLM, c4);
            if (tid == 0) o[r] = fi;
            for (int s2 = tid; s2 < c; s2 += 128)
                if (cidx[s2] == fi) cdd[s2] = 1e38f;
            __syncthreads();
        }
    }
}

// ---------------- FP 3-NN interpolation + skip concat (packed IO) ----------------
__global__ __launch_bounds__(256)
void fp_interp(const uint4* __restrict__ cf, const float* __restrict__ cp,
               const float* __restrict__ fpos, const uint4* __restrict__ sf,
               int nc, int nf, uint4* __restrict__ fin)
{
    __shared__ float sp[2048 * 3];
    const int bpb = nf >> 8;
    const int b = blockIdx.x / bpb;
    const int i = (blockIdx.x % bpb) * 256 + threadIdx.x;
    for (int t = threadIdx.x; t < nc * 3; t += 256) sp[t] = cp[(size_t)b * nc * 3 + t];
    __syncthreads();
    const float px = fpos[((size_t)b * nf + i) * 3];
    const float py = fpos[((size_t)b * nf + i) * 3 + 1];
    const float pz = fpos[((size_t)b * nf + i) * 3 + 2];
    float bd0 = 1e38f, bd1 = 1e38f, bd2 = 1e38f;
    int bi0 = 0, bi1 = 0, bi2 = 0;
    for (int j = 0; j < nc; j++) {
        float dx = px - sp[j * 3], dy = py - sp[j * 3 + 1], dz = pz - sp[j * 3 + 2];
        float d = dx * dx + dy * dy + dz * dz;
        if (d < bd0)      { bd2 = bd1; bi2 = bi1; bd1 = bd0; bi1 = bi0; bd0 = d; bi0 = j; }
        else if (d < bd1) { bd2 = bd1; bi2 = bi1; bd1 = d; bi1 = j; }
        else if (d < bd2) { bd2 = d; bi2 = j; }
    }
    const float w0 = 1.f / fmaxf(bd0, 1e-16f);
    const float w1 = 1.f / fmaxf(bd1, 1e-16f);
    const float w2 = 1.f / fmaxf(bd2, 1e-16f);
    const float rws = 1.f / (w0 + w1 + w2);
    const uint4* f0 = cf + ((size_t)b * nc + bi0) * 32;
    const uint4* f1 = cf + ((size_t)b * nc + bi1) * 32;
    const uint4* f2 = cf + ((size_t)b * nc + bi2) * 32;
    const uint4* s4 = sf + ((size_t)b * nf + i) * 32;
    uint4* o4 = fin + ((size_t)b * nf + i) * 64;
#pragma unroll 8
    for (int u = 0; u < 32; u++) {
        uint4 a = f0[u], bb = f1[u], cc = f2[u];
        float ra = (w0 * (bf2f(a.x & 0xffff) + bf2f(a.z & 0xffff))
                  + w1 * (bf2f(bb.x & 0xffff) + bf2f(bb.z & 0xffff))
                  + w2 * (bf2f(cc.x & 0xffff) + bf2f(cc.z & 0xffff))) * rws;
        float rb = (w0 * (bf2f(a.x >> 16) + bf2f(a.z >> 16))
                  + w1 * (bf2f(bb.x >> 16) + bf2f(bb.z >> 16))
                  + w2 * (bf2f(cc.x >> 16) + bf2f(cc.z >> 16))) * rws;
        float rc = (w0 * (bf2f(a.y & 0xffff) + bf2f(a.w & 0xffff))
                  + w1 * (bf2f(bb.y & 0xffff) + bf2f(bb.w & 0xffff))
                  + w2 * (bf2f(cc.y & 0xffff) + bf2f(cc.w & 0xffff))) * rws;
        float rd = (w0 * (bf2f(a.y >> 16) + bf2f(a.w >> 16))
                  + w1 * (bf2f(bb.y >> 16) + bf2f(bb.w >> 16))
                  + w2 * (bf2f(cc.y >> 16) + bf2f(cc.w >> 16))) * rws;
        uint4 r;
        split2(ra, rb, r.x, r.z);
        split2(rc, rd, r.y, r.w);
        o4[u] = r;
        o4[32 + u] = s4[u];
    }
}

// ---------------- host ----------------
extern "C" void kernel_launch(void* const* d_in, const int* in_sizes, int n_in,
                              void* d_out, int out_size)
{
    const float* x      = (const float*)d_in[0];
    const float* pos0   = (const float*)d_in[1];
    const float* lin_w  = (const float*)d_in[3];
    const float* lin_b  = (const float*)d_in[4];
    const float* sa_w1  = (const float*)d_in[5];
    const float* sa_b1  = (const float*)d_in[6];
    const float* sa_g1  = (const float*)d_in[7];
    const float* sa_be1 = (const float*)d_in[8];
    const float* sa_w2  = (const float*)d_in[9];
    const float* sa_b2  = (const float*)d_in[10];
    const float* sa_g2  = (const float*)d_in[11];
    const float* sa_be2 = (const float*)d_in[12];
    const float* fp_w1  = (const float*)d_in[13];
    const float* fp_b1  = (const float*)d_in[14];
    const float* fp_g1  = (const float*)d_in[15];
    const float* fp_be1 = (const float*)d_in[16];
    const float* fp_w2  = (const float*)d_in[17];
    const float* fp_b2  = (const float*)d_in[18];
    const float* fp_g2  = (const float*)d_in[19];
    const float* fp_be2 = (const float*)d_in[20];
    const float* lo_w1  = (const float*)d_in[21];
    const float* lo_b1  = (const float*)d_in[22];
    const float* lo_g1  = (const float*)d_in[23];
    const float* lo_be1 = (const float*)d_in[24];
    const float* lo_w2  = (const float*)d_in[25];
    const float* lo_b2  = (const float*)d_in[26];
    const float* lo_g2  = (const float*)d_in[27];
    const float* lo_be2 = (const float*)d_in[28];
    float* out = (float*)d_out;

    float* buf = nullptr;
    cudaGetSymbolAddress((void**)&buf, g_buf);

    uint4* featPk[4] = { (uint4*)(buf + OFF_FEAT0), (uint4*)(buf + OFF_FEAT1),
                         (uint4*)(buf + OFF_FEAT2), (uint4*)(buf + OFF_FEAT3) };
    const float* posl[4] = { pos0, buf + OFF_POS1, buf + OFF_POS2, buf + OFF_POS3 };
    int* cntL[3]  = { (int*)(buf + OFF_CNT0), (int*)(buf + OFF_CNT1), (int*)(buf + OFF_CNT2) };
    int* ofsL[3]  = { (int*)(buf + OFF_OFS0), (int*)(buf + OFF_OFS1), (int*)(buf + OFF_OFS2) };
    int* nbdL[3]  = { (int*)(buf + OFF_NBD0), (int*)(buf + OFF_NBD1), (int*)(buf + OFF_NBD2) };
    int* rmpL[3]  = { (int*)(buf + OFF_RMP0), (int*)(buf + OFF_RMP1), (int*)(buf + OFF_RMP2) };
    unsigned* stgL[3] = { (unsigned*)(buf + OFF_STG0), (unsigned*)(buf + OFF_STG1),
                          (unsigned*)(buf + OFF_STG2) };
    int* drL[3]   = { (int*)(buf + OFF_DR0), (int*)(buf + OFF_DR1), (int*)(buf + OFF_DR2) };
    uint4* h1Pk  = (uint4*)(buf + OFF_H1);
    uint4* finPk = (uint4*)(buf + OFF_FIN);
    uint4* f1Pk  = (uint4*)(buf + OFF_F1);
    uint4* xfPk  = (uint4*)(buf + OFF_XF);
    unsigned* wtBase = (unsigned*)(buf + OFF_WT);

    const int nlev[4] = {4096, 2048, 1024, 512};

    cudaStream_t s1;
    cudaStreamCreateWithFlags(&s1, cudaStreamNonBlocking);
    cudaEvent_t eFork, eK[3];
    cudaEventCreateWithFlags(&eFork, cudaEventDisableTiming);
    for (int l = 0; l < 3; l++) cudaEventCreateWithFlags(&eK[l], cudaEventDisableTiming);

    cudaEventRecord(eFork, 0);
    cudaStreamWaitEvent(s1, eFork, 0);

    // ---- geometry + compaction chain on s1 ----
    for (int l = 0; l < 3; l++) {
        int n = nlev[l], m = nlev[l + 1];
        int nC = NBATCH * m;
        if (l == 0)      fps_kernel<16><<<NBATCH, 256, 0, s1>>>(posl[0], n, m, (float*)posl[1]);
        else if (l == 1) fps_kernel<8><<<NBATCH, 256, 0, s1>>>(posl[1], n, m, (float*)posl[2]);
        else             fps_kernel<4><<<NBATCH, 256, 0, s1>>>(posl[2], n, m, (float*)posl[3]);
        knn_ball<<<nC, 128, 0, s1>>>(posl[l], posl[l + 1], n, m, nbdL[l], cntL[l]);
        scan_offsets<<<1, 256, 0, s1>>>(cntL[l], nC, ofsL[l], drL[l]);
        build_rowmap<<<nC, 64, 0, s1>>>(cntL[l], ofsL[l], nbdL[l], rmpL[l]);
        stage_init<<<(nC * 128 + 255) / 256, 256, 0, s1>>>(stgL[l], nC * 128);
        cudaEventRecord(eK[l], s1);
    }

    // ---- main stream: weights + lin_in ----
    {
        WTable tb;
        int cur = 0, e = 0;
        auto add = [&](const float* src, unsigned off, int K, int N, int Kp) {
            tb.d[e].src = src; tb.d[e].dstOff = off;
            tb.d[e].K = K; tb.d[e].N = N; tb.d[e].Kp = Kp; tb.d[e].start = cur;
            cur += N * (Kp >> 4) * 4;
            e++;
        };
        add(lin_w, WTO_LIN, 16, 128, 16);
        for (int l = 0; l < 3; l++) {
            add(sa_w1 + (size_t)l * 131 * 131, WTO_SAW1 + l * 18864, 131, 131, 144);
            add(sa_w2 + (size_t)l * 131 * 128, WTO_SAW2 + l * 18432, 131, 128, 144);
            add(fp_w1 + (size_t)l * 256 * 256, WTO_FPW1 + l * 65536, 256, 256, 256);
            add(fp_w2 + (size_t)l * 256 * 128, WTO_FPW2 + l * 32768, 256, 128, 256);
        }
        add(lo_w1, WTO_LOW1, 128, 128, 128);
        tb.total = cur;
        wconv_all<<<(cur + 255) / 256, 256>>>(tb, wtBase);
    }
    {
        dim3 grid(2, (NBATCH * 4096) / 128);
        gemm_tc<0, 0, 4><<<grid, 256>>>(x, 16, nullptr, (uint4*)(wtBase + WTO_LIN),
                                        lin_b, nullptr, nullptr,
                                        (unsigned*)featPk[0], 128, NBATCH * 4096, 128, 16,
                                        nullptr, nullptr, nullptr, nullptr, 0, 0, nullptr);
    }

    // ---- SA levels (compacted rows, join geometry per level) ----
    for (int l = 0; l < 3; l++) {
        int n = nlev[l], m = nlev[l + 1];
        int nC = NBATCH * m;
        int rowsMax = nC * KNB;
        cudaStreamWaitEvent(0, eK[l], 0);
        {
            // NT=3 -> BN=48; 3 tiles cover exactly 144 = KpOut columns (vs 192 at BN=64)
            dim3 grid(3, rowsMax / 128);
            gemm_tc<1, 2, 3><<<grid, 256>>>(nullptr, 0, nullptr,
                                            (uint4*)(wtBase + WTO_SAW1 + l * 18864),
                                            sa_b1 + l * 131, sa_g1 + l * 131, sa_be1 + l * 131,
                                            (unsigned*)h1Pk, 144, rowsMax, 131, 144,
                                            featPk[l], posl[l], posl[l + 1], rmpL[l],
                                            n, m, drL[l]);
        }
        {
            dim3 grid(2, rowsMax / 128);
            gemm_tc<2, 1, 4><<<grid, 256>>>(nullptr, 0, h1Pk,
                                            (uint4*)(wtBase + WTO_SAW2 + l * 18432),
                                            sa_b2 + l * 128, sa_g2 + l * 128, sa_be2 + l * 128,
                                            stgL[l], 128, rowsMax, 128, 144,
                                            nullptr, nullptr, nullptr, rmpL[l],
                                            n, m, drL[l]);
        }
        stage_to_pack<<<(nC * 64 + 255) / 256, 256>>>(stgL[l], nC, (unsigned*)featPk[l + 1]);
    }

    // ---- FP levels ----
    const uint4* cfeat = featPk[3];
    for (int step = 0; step < 3; step++) {
        int mi = 2 - step;
        int nc = nlev[mi + 1], nf = nlev[mi];
        fp_interp<<<NBATCH * (nf / 256), 256>>>(cfeat, posl[mi + 1], posl[mi],
                                                featPk[mi], nc, nf, finPk);
        int rows = NBATCH * nf;
        {
            dim3 grid(4, rows / 128);
            gemm_tc<1, 1, 4><<<grid, 256>>>(nullptr, 0, finPk,
                                            (uint4*)(wtBase + WTO_FPW1 + mi * 65536),
                                            fp_b1 + mi * 256, fp_g1 + mi * 256, fp_be1 + mi * 256,
                                            (unsigned*)f1Pk, 256, rows, 256, 256,
                                            nullptr, nullptr, nullptr, nullptr, 0, 0, nullptr);
        }
        {
            dim3 grid(2, rows / 128);
            gemm_tc<1, 1, 4><<<grid, 256>>>(nullptr, 0, f1Pk,
                                            (uint4*)(wtBase + WTO_FPW2 + mi * 32768),
                                            fp_b2 + mi * 128, fp_g2 + mi * 128, fp_be2 + mi * 128,
                                            (unsigned*)xfPk, 128, rows, 128, 256,
                                            nullptr, nullptr, nullptr, nullptr, 0, 0, nullptr);
        }
        cfeat = xfPk;
    }

    // ---- final MLP ----
    {
        dim3 grid(2, (NBATCH * 4096) / 128);
        gemm_tc<1, 1, 4><<<grid, 256>>>(nullptr, 0, xfPk, (uint4*)(wtBase + WTO_LOW1),
                                        lo_b1, lo_g1, lo_be1,
                                        (unsigned*)f1Pk, 128, NBATCH * 4096, 128, 128,
                                        nullptr, nullptr, nullptr, nullptr, 0, 0, nullptr);
    }
    final_out<<<(NBATCH * 4096) / 32, 256>>>(f1Pk, lo_w2, lo_b2, lo_g2, lo_be2,
                                             out, NBATCH * 4096);
}

// round 16
// speedup vs baseline: 1.1025x; 1.0555x over previous
#include <cuda_runtime.h>
#include <cuda_bf16.h>
#include <cstddef>

#define NBATCH 4
#define KNB 64
#define KCAP 320
#define FULLM 0xffffffffu

// ---------------- scratch layout (floats) ----------------
#define OFF_FEAT0 0ull
#define OFF_FEAT1 2097152ull
#define OFF_FEAT2 3145728ull
#define OFF_FEAT3 3670016ull
#define OFF_POS1  3932160ull
#define OFF_POS2  3956736ull
#define OFF_POS3  3969024ull
#define OFF_FIN   4499456ull
#define OFF_F1    8693760ull
#define OFF_XF    12888064ull
#define OFF_WT    14985216ull
#define OFF_H1    15509504ull
// per-level compaction scratch
#define OFF_CNT0 91400192ull
#define OFF_OFS0 91408384ull
#define OFF_NBD0 91416584ull
#define OFF_RMP0 91940872ull
#define OFF_STG0 92465160ull
#define OFF_DR0  93513736ull
#define OFF_CNT1 93513744ull
#define OFF_OFS1 93517840ull
#define OFF_NBD1 93521944ull
#define OFF_RMP1 93784088ull
#define OFF_STG1 94046232ull
#define OFF_DR1  94570520ull
#define OFF_CNT2 94570528ull
#define OFF_OFS2 94572576ull
#define OFF_NBD2 94574632ull
#define OFF_RMP2 94705704ull
#define OFF_STG2 94836776ull
#define OFF_DR2  95098920ull
#define TOTAL_FLOATS 95098944ull

__device__ __align__(256) float g_buf[TOTAL_FLOATS];

// ---- WT sub-offsets (uint32 elements inside WT region) ----
#define WTO_LIN   0
#define WTO_SAW1  2048
#define WTO_SAW2  58640
#define WTO_FPW1  113936
#define WTO_FPW2  310544
#define WTO_LOW1  408848

// ---------------- bf16 helpers ----------------
__device__ __forceinline__ float bf2f(unsigned s16) {
    return __uint_as_float(s16 << 16);
}
__device__ __forceinline__ void split2(float a, float b, unsigned& hw, unsigned& lw) {
    __nv_bfloat16 ah = __float2bfloat16(a), bh = __float2bfloat16(b);
    float ar = a - __bfloat162float(ah);
    float br = b - __bfloat162float(bh);
    hw = (unsigned)__bfloat16_as_ushort(ah) | ((unsigned)__bfloat16_as_ushort(bh) << 16);
    lw = (unsigned)__bfloat16_as_ushort(__float2bfloat16(ar))
       | ((unsigned)__bfloat16_as_ushort(__float2bfloat16(br)) << 16);
}
__device__ __forceinline__ void store_pair(unsigned* C, int KpOut, int row, int g0,
                                           float v0, float v1) {
    unsigned hw, lw;
    split2(v0, v1, hw, lw);
    size_t off = ((size_t)row * (KpOut >> 2) + ((g0 >> 4) << 2) + ((g0 & 7) >> 1)) * 4
               + ((g0 >> 3) & 1);
    C[off]     = hw;
    C[off + 2] = lw;
}

// monotonic fp32<->uint encoding (order-preserving for atomicMax)
__device__ __forceinline__ unsigned encf(float f) {
    unsigned b = __float_as_uint(f);
    return (b & 0x80000000u) ? ~b : (b | 0x80000000u);
}
__device__ __forceinline__ float decf(unsigned u) {
    unsigned b = (u & 0x80000000u) ? (u & 0x7fffffffu) : ~u;
    return __uint_as_float(b);
}

__device__ __forceinline__ void mma16(float* c, const unsigned* a, unsigned b0, unsigned b1) {
    asm volatile(
        "mma.sync.aligned.m16n8k16.row.col.f32.bf16.bf16.f32 "
        "{%0,%1,%2,%3}, {%4,%5,%6,%7}, {%8,%9}, {%0,%1,%2,%3};"
        : "+f"(c[0]), "+f"(c[1]), "+f"(c[2]), "+f"(c[3])
        : "r"(a[0]), "r"(a[1]), "r"(a[2]), "r"(a[3]), "r"(b0), "r"(b1));
}

__device__ __forceinline__ int swz(int row, int t) {
    return t ^ ((row ^ (row >> 2)) & 3);
}

// ---------------- fused weight preprocess ----------------
struct WDesc { const float* src; unsigned dstOff; int K; int N; int Kp; int start; };
struct WTable { WDesc d[14]; int total; };

__global__ void wconv_all(WTable tb, unsigned* __restrict__ wtBase)
{
    int idx = blockIdx.x * blockDim.x + threadIdx.x;
    if (idx >= tb.total) return;
    int di = 0;
#pragma unroll
    for (int i = 1; i < 14; i++) if (idx >= tb.d[i].start) di = i;
    const WDesc D = tb.d[di];
    int e = idx - D.start;
    int t = e & 3;
    int c = (e >> 2) % (D.Kp >> 4);
    int n = e / ((D.Kp >> 4) * 4);
    int k0 = 16 * c + 2 * t;
    const float* W = D.src;
    float v0 = (k0     < D.K) ? W[(size_t)(k0    ) * D.N + n] : 0.f;
    float v1 = (k0 + 1 < D.K) ? W[(size_t)(k0 + 1) * D.N + n] : 0.f;
    float v2 = (k0 + 8 < D.K) ? W[(size_t)(k0 + 8) * D.N + n] : 0.f;
    float v3 = (k0 + 9 < D.K) ? W[(size_t)(k0 + 9) * D.N + n] : 0.f;
    uint4 u;
    split2(v0, v1, u.x, u.z);
    split2(v2, v3, u.y, u.w);
    ((uint4*)(wtBase + D.dstOff))[e] = u;
}

// ---------------- tensor-core GEMM (3xBF16), packed hi/lo I/O, double-buffered ----------------
// EPI: 0 = relu, 1 = relu+bn, 2 = relu+bn + segmented max via atomicMax into staging (Cpk).
// ASRC: 0 = fp32 A (lda), 1 = packed A, 2 = gather via rowmap (aux) from packed feat + pos delta.
// Loader rebalanced across ALL 256 threads: each thread = 2 A-uint4 (row tid>>1)
// + 1 W-uint4 (col tid>>2) per chunk.
template<int EPI, int ASRC>
__global__ __launch_bounds__(256)
void gemm_tc(const float* __restrict__ Afp, int lda,
             const uint4* __restrict__ Apk,
             const uint4* __restrict__ Wt,
             const float* __restrict__ bias, const float* __restrict__ gam,
             const float* __restrict__ bet,
             unsigned* __restrict__ Cpk, int KpOut, int M, int N, int Kp,
             const uint4* __restrict__ featPk, const float* __restrict__ posL,
             const float* __restrict__ q, const int* __restrict__ aux,
             int nPts, int mCen, const int* __restrict__ dR)
{
    __shared__ union SMU {
        struct { uint4 As4[2][512]; uint4 Ws4[2][256]; } mm;
        struct { float ep[128][66]; int sbc[128]; } epi;
    } sm;

    const int tid  = threadIdx.x;
    const int lane = tid & 31;
    const int warp = tid >> 5;
    const int mwarp = warp >> 1;
    const int nwarp = warp & 1;
    const int gid = lane >> 2;
    const int tig = lane & 3;
    const int bm = blockIdx.y * 128;
    const int bn = blockIdx.x * 64;

    int R = 0x7fffffff;
    if (ASRC == 2 || EPI == 2) {
        R = __ldg(dR);
        if (bm >= R) return;
    }

    float acc[2][4][4];
#pragma unroll
    for (int mt = 0; mt < 2; mt++)
#pragma unroll
        for (int nt = 0; nt < 4; nt++)
#pragma unroll
            for (int e = 0; e < 4; e++) acc[mt][nt][e] = 0.f;

    // loader roles (all 256 threads):
    const int ar = tid >> 1;          // A row 0..127 (2 threads per row)
    const int ta = (tid & 1) * 2;     // this thread's A uint4 pair: t = ta, ta+1
    const int wc = tid >> 2;          // W col 0..63 (4 threads per col)
    const int wt = tid & 3;           // this thread's W uint4 index

    int gj = -1, gb = 0, gbc = 0;
    if (ASRC == 2) {
        int gm = bm + ar;
        if (gm < R) {
            int rm = aux[gm];
            gj  = rm & 0xffff;
            gbc = rm >> 16;
            gb  = gbc / mCen;
        }
    }

    const int rowU4 = Kp >> 2;
    const int C = Kp >> 4;
    const int gnW = bn + wc;
    uint4 stA0, stA1, stW;

    auto loadStage = [&](int c) {
        const int k0 = c << 4;
        // ---- A: 2 uint4 for row ar ----
        if (ASRC == 1) {
            const uint4* p = Apk + (size_t)(bm + ar) * rowU4 + c * 4 + ta;
            stA0 = p[0]; stA1 = p[1];
        } else if (ASRC == 2) {
            if (gj < 0) {
                stA0 = make_uint4(0, 0, 0, 0);
                stA1 = make_uint4(0, 0, 0, 0);
            } else if (k0 < 128) {
                const uint4* p = featPk + ((size_t)gb * nPts + gj) * 32 + c * 4 + ta;
                stA0 = p[0]; stA1 = p[1];
            } else {
                if (ta == 0) {
                    const float* pp = posL + ((size_t)gb * nPts + gj) * 3;
                    const float* qq = q + (size_t)gbc * 3;
                    float d0 = pp[0] - qq[0], d1 = pp[1] - qq[1], d2 = pp[2] - qq[2];
                    unsigned h01, l01, h2z, l2z;
                    split2(d0, d1, h01, l01);
                    split2(d2, 0.f, h2z, l2z);
                    stA0 = make_uint4(h01, 0, l01, 0);
                    stA1 = make_uint4(h2z, 0, l2z, 0);
                } else {
                    stA0 = make_uint4(0, 0, 0, 0);
                    stA1 = make_uint4(0, 0, 0, 0);
                }
            }
        } else {
            // fp32 A: this thread covers av-blocks i = ta>>1 and (ta>>1)+2
            const float4* fp = (const float4*)(Afp + (size_t)(bm + ar) * lda + k0);
            float4 va = fp[(ta >> 1)];
            float4 vb = fp[(ta >> 1) + 2];
            float a0 = va.x, a1 = va.y, a2 = va.z, a3 = va.w;
            float b0 = vb.x, b1 = vb.y, b2 = vb.z, b3 = vb.w;
            split2(a0, a1, stA0.x, stA0.z);
            split2(b0, b1, stA0.y, stA0.w);
            split2(a2, a3, stA1.x, stA1.z);
            split2(b2, b3, stA1.y, stA1.w);
        }
        // ---- W: 1 uint4 for col wc ----
        if (gnW < N) {
            stW = Wt[(size_t)gnW * rowU4 + c * 4 + wt];
        } else {
            stW = make_uint4(0, 0, 0, 0);
        }
    };
    auto storeStage = [&](int b) {
        sm.mm.As4[b][ar * 4 + swz(ar, ta)]     = stA0;
        sm.mm.As4[b][ar * 4 + swz(ar, ta + 1)] = stA1;
        sm.mm.Ws4[b][wc * 4 + swz(wc, wt)]     = stW;
    };

    loadStage(0);
    storeStage(0);
    __syncthreads();

    for (int c = 0; c < C; c++) {
        const int cb = c & 1;
        if (c + 1 < C) loadStage(c + 1);

        unsigned ah[2][4], al[2][4];
#pragma unroll
        for (int mt = 0; mt < 2; mt++) {
            int mr  = mwarp * 32 + mt * 16 + gid;
            int mr8 = mr + 8;
            uint4 ua = sm.mm.As4[cb][mr * 4 + swz(mr, tig)];
            uint4 ub = sm.mm.As4[cb][mr8 * 4 + swz(mr8, tig)];
            ah[mt][0] = ua.x; ah[mt][1] = ub.x; ah[mt][2] = ua.y; ah[mt][3] = ub.y;
            al[mt][0] = ua.z; al[mt][1] = ub.z; al[mt][2] = ua.w; al[mt][3] = ub.w;
        }
#pragma unroll
        for (int nt = 0; nt < 4; nt++) {
            int nc = nwarp * 32 + nt * 8 + gid;
            uint4 uw = sm.mm.Ws4[cb][nc * 4 + swz(nc, tig)];
#pragma unroll
            for (int mt = 0; mt < 2; mt++) {
                mma16(acc[mt][nt], ah[mt], uw.x, uw.y);
                mma16(acc[mt][nt], ah[mt], uw.z, uw.w);
                mma16(acc[mt][nt], al[mt], uw.x, uw.y);
            }
        }

        if (c + 1 < C) storeStage(cb ^ 1);
        __syncthreads();
    }

    const float inv = rsqrtf(1.f + 1e-5f);

    if (EPI < 2) {
#pragma unroll
        for (int mt = 0; mt < 2; mt++) {
#pragma unroll
            for (int nt = 0; nt < 4; nt++) {
                int g0 = bn + nwarp * 32 + nt * 8 + 2 * tig;
                if (g0 + 1 >= KpOut && g0 >= N) continue;
#pragma unroll
                for (int rr = 0; rr < 2; rr++) {
                    int row = bm + mwarp * 32 + mt * 16 + gid + rr * 8;
                    float v0 = acc[mt][nt][rr * 2];
                    float v1 = acc[mt][nt][rr * 2 + 1];
                    if (g0 < N) {
                        v0 = fmaxf(v0 + bias[g0], 0.f);
                        if (EPI == 1) v0 = gam[g0] * v0 * inv + bet[g0];
                    } else v0 = 0.f;
                    if (g0 + 1 < N) {
                        v1 = fmaxf(v1 + bias[g0 + 1], 0.f);
                        if (EPI == 1) v1 = gam[g0 + 1] * v1 * inv + bet[g0 + 1];
                    } else v1 = 0.f;
                    if (g0 + 1 < KpOut + 1 && g0 < KpOut)
                        store_pair(Cpk, KpOut, row, g0, v0, v1);
                }
            }
        }
    } else {
        // segmented max epilogue: bn values -> smem tile -> per-center atomicMax staging
        if (tid < 128) {
            int r = bm + tid;
            sm.epi.sbc[tid] = (r < R) ? (aux[r] >> 16) : -1;
        }
#pragma unroll
        for (int mt = 0; mt < 2; mt++) {
#pragma unroll
            for (int nt = 0; nt < 4; nt++) {
#pragma unroll
                for (int e = 0; e < 4; e++) {
                    int rl = mwarp * 32 + mt * 16 + gid + (e >> 1) * 8;
                    int cl = nwarp * 32 + nt * 8 + 2 * tig + (e & 1);
                    int gn = bn + cl;
                    float v = acc[mt][nt][e] + bias[gn];
                    v = fmaxf(v, 0.f);
                    v = gam[gn] * v * inv + bet[gn];
                    sm.epi.ep[rl][cl] = v;
                }
            }
        }
        __syncthreads();
        const int col = tid & 63;
        const int r0 = (tid >> 6) * 32;
        int cur = -1;
        float mx = -1e30f;
#pragma unroll 4
        for (int rl = r0; rl < r0 + 32; rl++) {
            int bc = sm.epi.sbc[rl];
            if (bc != cur) {
                if (cur >= 0)
                    atomicMax(&Cpk[(size_t)cur * 128 + bn + col], encf(mx));
                cur = bc;
                mx = -1e30f;
            }
            if (bc >= 0) mx = fmaxf(mx, sm.epi.ep[rl][col]);
        }
        if (cur >= 0)
            atomicMax(&Cpk[(size_t)cur * 128 + bn + col], encf(mx));
    }
}

// ---------------- staging helpers ----------------
__global__ void stage_init(unsigned* __restrict__ st, int n)
{
    int idx = blockIdx.x * blockDim.x + threadIdx.x;
    if (idx < n) st[idx] = encf(-1e30f);
}

__global__ void stage_to_pack(const unsigned* __restrict__ st, int nC,
                              unsigned* __restrict__ outPk)
{
    int idx = blockIdx.x * blockDim.x + threadIdx.x;
    if (idx >= nC * 64) return;
    int center = idx >> 6;
    int g0 = (idx & 63) * 2;
    float v0 = decf(st[center * 128 + g0]);
    float v1 = decf(st[center * 128 + g0 + 1]);
    store_pair(outPk, 128, center, g0, v0, v1);
}

// ---------------- compaction: scan + rowmap build ----------------
__global__ void scan_offsets(const int* __restrict__ cnt, int nC,
                             int* __restrict__ off, int* __restrict__ dR)
{
    __shared__ int part[256];
    const int tid = threadIdx.x;
    const int chunk = (nC + 255) / 256;
    const int base = tid * chunk;
    int s = 0;
    for (int i = 0; i < chunk; i++) {
        int j = base + i;
        if (j < nC) s += cnt[j];
    }
    part[tid] = s;
    __syncthreads();
    if (tid == 0) {
        int acc = 0;
        for (int i = 0; i < 256; i++) { int t = part[i]; part[i] = acc; acc += t; }
        dR[0] = acc;
    }
    __syncthreads();
    int acc = part[tid];
    for (int i = 0; i < chunk; i++) {
        int j = base + i;
        if (j < nC) { off[j] = acc; acc += cnt[j]; }
    }
}

__global__ void build_rowmap(const int* __restrict__ cnt, const int* __restrict__ off,
                             const int* __restrict__ nbrd, int* __restrict__ rowmap)
{
    const int bc = blockIdx.x;
    const int t = threadIdx.x;
    if (t < cnt[bc]) rowmap[off[bc] + t] = nbrd[bc * 64 + t] | (bc << 16);
}

// ---------------- final tiny layer ----------------
__global__ __launch_bounds__(256)
void final_out(const uint4* __restrict__ Apk, const float* __restrict__ W,
               const float* __restrict__ bias, const float* __restrict__ gam,
               const float* __restrict__ bet, float* __restrict__ out, int M)
{
    __shared__ float sw[256];
    const int tid = threadIdx.x;
    sw[tid] = W[tid];
    __syncthreads();
    const int row = blockIdx.x * 32 + (tid >> 3);
    const int sub = tid & 7;
    if (row >= M) return;
    const uint4* a4 = Apk + (size_t)row * 32 + sub * 4;
    float acc0 = 0.f, acc1 = 0.f;
#pragma unroll
    for (int i = 0; i < 4; i++) {
        uint4 u = a4[i];
        int g = sub * 4 + i;
        int e0 = 16 * (g >> 2) + 2 * (g & 3);
        float va = bf2f(u.x & 0xffff) + bf2f(u.z & 0xffff);
        float vb = bf2f(u.x >> 16)    + bf2f(u.z >> 16);
        float vc = bf2f(u.y & 0xffff) + bf2f(u.w & 0xffff);
        float vd = bf2f(u.y >> 16)    + bf2f(u.w >> 16);
        acc0 += va * sw[e0 * 2]        + vb * sw[(e0 + 1) * 2]
              + vc * sw[(e0 + 8) * 2]  + vd * sw[(e0 + 9) * 2];
        acc1 += va * sw[e0 * 2 + 1]       + vb * sw[(e0 + 1) * 2 + 1]
              + vc * sw[(e0 + 8) * 2 + 1] + vd * sw[(e0 + 9) * 2 + 1];
    }
#pragma unroll
    for (int off = 4; off; off >>= 1) {
        acc0 += __shfl_down_sync(FULLM, acc0, off);
        acc1 += __shfl_down_sync(FULLM, acc1, off);
    }
    if (sub == 0) {
        const float inv = rsqrtf(1.f + 1e-5f);
        float v0 = fmaxf(acc0 + bias[0], 0.f);
        float v1 = fmaxf(acc1 + bias[1], 0.f);
        v0 = gam[0] * v0 * inv + bet[0];
        v1 = gam[1] * v1 * inv + bet[1];
        out[(size_t)row * 2]     = v0;
        out[(size_t)row * 2 + 1] = v1;
    }
}

// ---------------- farthest point sampling (256 threads, redux, 1 barrier/step) ----------------
template<int PER>
__global__ __launch_bounds__(256)
void fps_kernel(const float* __restrict__ pos, int n, int m, float* __restrict__ qout)
{
    const int b = blockIdx.x, tid = threadIdx.x;
    const int lane = tid & 31, warp = tid >> 5;
    const float* P = pos + (size_t)b * n * 3;
    float* Q = qout + (size_t)b * m * 3;
    float px[PER], py[PER], pz[PER], dmin[PER];
#pragma unroll
    for (int u = 0; u < PER; u++) {
        int i = tid + 256 * u;
        px[u] = P[i * 3]; py[u] = P[i * 3 + 1]; pz[u] = P[i * 3 + 2];
        dmin[u] = 1e30f;
    }
    __shared__ unsigned s_v[2][8];
    __shared__ int      s_i[2][8];

    float qx = P[0], qy = P[1], qz = P[2];
    if (tid == 0) { Q[0] = qx; Q[1] = qy; Q[2] = qz; }

    for (int s = 1; s < m; s++) {
        float bv = -1e31f; int bi = 0;
#pragma unroll
        for (int u = 0; u < PER; u++) {
            float dx = px[u] - qx, dy = py[u] - qy, dz = pz[u] - qz;
            float d = dx * dx + dy * dy + dz * dz;
            d = fminf(dmin[u], d);
            dmin[u] = d;
            if (d > bv) { bv = d; bi = tid + 256 * u; }   // ascending u: lowest idx on ties
        }
        unsigned vb = __float_as_uint(bv);
        unsigned vmax = __reduce_max_sync(FULLM, vb);
        int cand = (vb == vmax) ? bi : 0x7fffffff;
        int imin = __reduce_min_sync(FULLM, cand);
        const int par = s & 1;
        if (lane == 0) { s_v[par][warp] = vmax; s_i[par][warp] = imin; }
        __syncthreads();
        unsigned v8 = (lane < 8) ? s_v[par][lane] : 0u;
        unsigned vm8 = __reduce_max_sync(FULLM, v8);
        int c8 = (lane < 8 && v8 == vm8) ? s_i[par][lane] : 0x7fffffff;
        int fi = __reduce_min_sync(FULLM, c8);
        qx = P[fi * 3]; qy = P[fi * 3 + 1]; qz = P[fi * 3 + 2];
        if (tid == 0) { Q[s * 3] = qx; Q[s * 3 + 1] = qy; Q[s * 3 + 2] = qz; }
    }
}

// ---------------- ball-query: filter-then-select, dense output + counts ----------------
__global__ __launch_bounds__(128)
void knn_ball(const float* __restrict__ pos, const float* __restrict__ q,
              int n, int m, int* __restrict__ nbrd, int* __restrict__ cntArr)
{
    __shared__ int   cidx[KCAP];
    __shared__ float cdd[KCAP];
    __shared__ int   cnt;
    __shared__ unsigned w_v[4];
    __shared__ int      w_i[4];

    const int bc = blockIdx.x;
    const int tid = threadIdx.x;
    const float* P = pos + (size_t)(bc / m) * n * 3;
    const float qx = q[(size_t)bc * 3], qy = q[(size_t)bc * 3 + 1], qz = q[(size_t)bc * 3 + 2];

    if (tid == 0) cnt = 0;
    __syncthreads();

    for (int i = tid; i < n; i += 128) {
        float dx = P[i * 3] - qx, dy = P[i * 3 + 1] - qy, dz = P[i * 3 + 2] - qz;
        float d2 = dx * dx + dy * dy + dz * dz;
        if (d2 <= 4.0f) {
            int p = atomicAdd(&cnt, 1);
            if (p < KCAP) { cidx[p] = i; cdd[p] = d2; }
        }
    }
    __syncthreads();

    int c = cnt;
    if (c > KCAP) c = KCAP;
    int* o = nbrd + (size_t)bc * KNB;

    if (c <= KNB) {
        if (tid == 0) cntArr[bc] = c;
        if (tid < c) o[tid] = cidx[tid];
    } else {
        if (tid == 0) cntArr[bc] = KNB;
        for (int r = 0; r < KNB; r++) {
            float bv = 1e38f; int bi = 0x7fffffff;
            for (int s2 = tid; s2 < c; s2 += 128) {
                float v = cdd[s2];
                int oi = cidx[s2];
                if (v < bv || (v == bv && oi < bi)) { bv = v; bi = oi; }
            }
            unsigned vb = __float_as_uint(bv);
            unsigned vmin = __reduce_min_sync(FULLM, vb);
            int cand = (vb == vmin) ? bi : 0x7fffffff;
            int imin = __reduce_min_sync(FULLM, cand);
            if ((tid & 31) == 0) { w_v[tid >> 5] = vmin; w_i[tid >> 5] = imin; }
            __syncthreads();
            unsigned v4 = ((tid & 31) < 4) ? w_v[tid & 31] : 0xffffffffu;
            unsigned vm4 = __reduce_min_sync(FULLM, v4);
            int c4 = ((tid & 31) < 4 && v4 == vm4) ? w_i[tid & 31] : 0x7fffffff;
            int fi = __reduce_min_sync(FULLM, c4);
            if (tid == 0) o[r] = fi;
            for (int s2 = tid; s2 < c; s2 += 128)
                if (cidx[s2] == fi) cdd[s2] = 1e38f;
            __syncthreads();
        }
    }
}

// ---------------- FP 3-NN interpolation + skip concat (packed IO) ----------------
__global__ __launch_bounds__(256)
void fp_interp(const uint4* __restrict__ cf, const float* __restrict__ cp,
               const float* __restrict__ fpos, const uint4* __restrict__ sf,
               int nc, int nf, uint4* __restrict__ fin)
{
    __shared__ float sp[2048 * 3];
    const int bpb = nf >> 8;
    const int b = blockIdx.x / bpb;
    const int i = (blockIdx.x % bpb) * 256 + threadIdx.x;
    for (int t = threadIdx.x; t < nc * 3; t += 256) sp[t] = cp[(size_t)b * nc * 3 + t];
    __syncthreads();
    const float px = fpos[((size_t)b * nf + i) * 3];
    const float py = fpos[((size_t)b * nf + i) * 3 + 1];
    const float pz = fpos[((size_t)b * nf + i) * 3 + 2];
    float bd0 = 1e38f, bd1 = 1e38f, bd2 = 1e38f;
    int bi0 = 0, bi1 = 0, bi2 = 0;
    for (int j = 0; j < nc; j++) {
        float dx = px - sp[j * 3], dy = py - sp[j * 3 + 1], dz = pz - sp[j * 3 + 2];
        float d = dx * dx + dy * dy + dz * dz;
        if (d < bd0)      { bd2 = bd1; bi2 = bi1; bd1 = bd0; bi1 = bi0; bd0 = d; bi0 = j; }
        else if (d < bd1) { bd2 = bd1; bi2 = bi1; bd1 = d; bi1 = j; }
        else if (d < bd2) { bd2 = d; bi2 = j; }
    }
    const float w0 = 1.f / fmaxf(bd0, 1e-16f);
    const float w1 = 1.f / fmaxf(bd1, 1e-16f);
    const float w2 = 1.f / fmaxf(bd2, 1e-16f);
    const float rws = 1.f / (w0 + w1 + w2);
    const uint4* f0 = cf + ((size_t)b * nc + bi0) * 32;
    const uint4* f1 = cf + ((size_t)b * nc + bi1) * 32;
    const uint4* f2 = cf + ((size_t)b * nc + bi2) * 32;
    const uint4* s4 = sf + ((size_t)b * nf + i) * 32;
    uint4* o4 = fin + ((size_t)b * nf + i) * 64;
#pragma unroll 8
    for (int u = 0; u < 32; u++) {
        uint4 a = f0[u], bb = f1[u], cc = f2[u];
        float ra = (w0 * (bf2f(a.x & 0xffff) + bf2f(a.z & 0xffff))
                  + w1 * (bf2f(bb.x & 0xffff) + bf2f(bb.z & 0xffff))
                  + w2 * (bf2f(cc.x & 0xffff) + bf2f(cc.z & 0xffff))) * rws;
        float rb = (w0 * (bf2f(a.x >> 16) + bf2f(a.z >> 16))
                  + w1 * (bf2f(bb.x >> 16) + bf2f(bb.z >> 16))
                  + w2 * (bf2f(cc.x >> 16) + bf2f(cc.z >> 16))) * rws;
        float rc = (w0 * (bf2f(a.y & 0xffff) + bf2f(a.w & 0xffff))
                  + w1 * (bf2f(bb.y & 0xffff) + bf2f(bb.w & 0xffff))
                  + w2 * (bf2f(cc.y & 0xffff) + bf2f(cc.w & 0xffff))) * rws;
        float rd = (w0 * (bf2f(a.y >> 16) + bf2f(a.w >> 16))
                  + w1 * (bf2f(bb.y >> 16) + bf2f(bb.w >> 16))
                  + w2 * (bf2f(cc.y >> 16) + bf2f(cc.w >> 16))) * rws;
        uint4 r;
        split2(ra, rb, r.x, r.z);
        split2(rc, rd, r.y, r.w);
        o4[u] = r;
        o4[32 + u] = s4[u];
    }
}

// ---------------- host ----------------
extern "C" void kernel_launch(void* const* d_in, const int* in_sizes, int n_in,
                              void* d_out, int out_size)
{
    const float* x      = (const float*)d_in[0];
    const float* pos0   = (const float*)d_in[1];
    const float* lin_w  = (const float*)d_in[3];
    const float* lin_b  = (const float*)d_in[4];
    const float* sa_w1  = (const float*)d_in[5];
    const float* sa_b1  = (const float*)d_in[6];
    const float* sa_g1  = (const float*)d_in[7];
    const float* sa_be1 = (const float*)d_in[8];
    const float* sa_w2  = (const float*)d_in[9];
    const float* sa_b2  = (const float*)d_in[10];
    const float* sa_g2  = (const float*)d_in[11];
    const float* sa_be2 = (const float*)d_in[12];
    const float* fp_w1  = (const float*)d_in[13];
    const float* fp_b1  = (const float*)d_in[14];
    const float* fp_g1  = (const float*)d_in[15];
    const float* fp_be1 = (const float*)d_in[16];
    const float* fp_w2  = (const float*)d_in[17];
    const float* fp_b2  = (const float*)d_in[18];
    const float* fp_g2  = (const float*)d_in[19];
    const float* fp_be2 = (const float*)d_in[20];
    const float* lo_w1  = (const float*)d_in[21];
    const float* lo_b1  = (const float*)d_in[22];
    const float* lo_g1  = (const float*)d_in[23];
    const float* lo_be1 = (const float*)d_in[24];
    const float* lo_w2  = (const float*)d_in[25];
    const float* lo_b2  = (const float*)d_in[26];
    const float* lo_g2  = (const float*)d_in[27];
    const float* lo_be2 = (const float*)d_in[28];
    float* out = (float*)d_out;

    float* buf = nullptr;
    cudaGetSymbolAddress((void**)&buf, g_buf);

    uint4* featPk[4] = { (uint4*)(buf + OFF_FEAT0), (uint4*)(buf + OFF_FEAT1),
                         (uint4*)(buf + OFF_FEAT2), (uint4*)(buf + OFF_FEAT3) };
    const float* posl[4] = { pos0, buf + OFF_POS1, buf + OFF_POS2, buf + OFF_POS3 };
    int* cntL[3]  = { (int*)(buf + OFF_CNT0), (int*)(buf + OFF_CNT1), (int*)(buf + OFF_CNT2) };
    int* ofsL[3]  = { (int*)(buf + OFF_OFS0), (int*)(buf + OFF_OFS1), (int*)(buf + OFF_OFS2) };
    int* nbdL[3]  = { (int*)(buf + OFF_NBD0), (int*)(buf + OFF_NBD1), (int*)(buf + OFF_NBD2) };
    int* rmpL[3]  = { (int*)(buf + OFF_RMP0), (int*)(buf + OFF_RMP1), (int*)(buf + OFF_RMP2) };
    unsigned* stgL[3] = { (unsigned*)(buf + OFF_STG0), (unsigned*)(buf + OFF_STG1),
                          (unsigned*)(buf + OFF_STG2) };
    int* drL[3]   = { (int*)(buf + OFF_DR0), (int*)(buf + OFF_DR1), (int*)(buf + OFF_DR2) };
    uint4* h1Pk  = (uint4*)(buf + OFF_H1);
    uint4* finPk = (uint4*)(buf + OFF_FIN);
    uint4* f1Pk  = (uint4*)(buf + OFF_F1);
    uint4* xfPk  = (uint4*)(buf + OFF_XF);
    unsigned* wtBase = (unsigned*)(buf + OFF_WT);

    const int nlev[4] = {4096, 2048, 1024, 512};

    cudaStream_t s1;
    cudaStreamCreateWithFlags(&s1, cudaStreamNonBlocking);
    cudaEvent_t eFork, eK[3];
    cudaEventCreateWithFlags(&eFork, cudaEventDisableTiming);
    for (int l = 0; l < 3; l++) cudaEventCreateWithFlags(&eK[l], cudaEventDisableTiming);

    cudaEventRecord(eFork, 0);
    cudaStreamWaitEvent(s1, eFork, 0);

    // ---- geometry + compaction chain on s1 ----
    for (int l = 0; l < 3; l++) {
        int n = nlev[l], m = nlev[l + 1];
        int nC = NBATCH * m;
        if (l == 0)      fps_kernel<16><<<NBATCH, 256, 0, s1>>>(posl[0], n, m, (float*)posl[1]);
        else if (l == 1) fps_kernel<8><<<NBATCH, 256, 0, s1>>>(posl[1], n, m, (float*)posl[2]);
        else             fps_kernel<4><<<NBATCH, 256, 0, s1>>>(posl[2], n, m, (float*)posl[3]);
        knn_ball<<<nC, 128, 0, s1>>>(posl[l], posl[l + 1], n, m, nbdL[l], cntL[l]);
        scan_offsets<<<1, 256, 0, s1>>>(cntL[l], nC, ofsL[l], drL[l]);
        build_rowmap<<<nC, 64, 0, s1>>>(cntL[l], ofsL[l], nbdL[l], rmpL[l]);
        stage_init<<<(nC * 128 + 255) / 256, 256, 0, s1>>>(stgL[l], nC * 128);
        cudaEventRecord(eK[l], s1);
    }

    // ---- main stream: weights + lin_in ----
    {
        WTable tb;
        int cur = 0, e = 0;
        auto add = [&](const float* src, unsigned off, int K, int N, int Kp) {
            tb.d[e].src = src; tb.d[e].dstOff = off;
            tb.d[e].K = K; tb.d[e].N = N; tb.d[e].Kp = Kp; tb.d[e].start = cur;
            cur += N * (Kp >> 4) * 4;
            e++;
        };
        add(lin_w, WTO_LIN, 16, 128, 16);
        for (int l = 0; l < 3; l++) {
            add(sa_w1 + (size_t)l * 131 * 131, WTO_SAW1 + l * 18864, 131, 131, 144);
            add(sa_w2 + (size_t)l * 131 * 128, WTO_SAW2 + l * 18432, 131, 128, 144);
            add(fp_w1 + (size_t)l * 256 * 256, WTO_FPW1 + l * 65536, 256, 256, 256);
            add(fp_w2 + (size_t)l * 256 * 128, WTO_FPW2 + l * 32768, 256, 128, 256);
        }
        add(lo_w1, WTO_LOW1, 128, 128, 128);
        tb.total = cur;
        wconv_all<<<(cur + 255) / 256, 256>>>(tb, wtBase);
    }
    {
        dim3 grid(2, (NBATCH * 4096) / 128);
        gemm_tc<0, 0><<<grid, 256>>>(x, 16, nullptr, (uint4*)(wtBase + WTO_LIN),
                                     lin_b, nullptr, nullptr,
                                     (unsigned*)featPk[0], 128, NBATCH * 4096, 128, 16,
                                     nullptr, nullptr, nullptr, nullptr, 0, 0, nullptr);
    }

    // ---- SA levels (compacted rows, join geometry per level) ----
    for (int l = 0; l < 3; l++) {
        int n = nlev[l], m = nlev[l + 1];
        int nC = NBATCH * m;
        int rowsMax = nC * KNB;
        cudaStreamWaitEvent(0, eK[l], 0);
        {
            dim3 grid(3, rowsMax / 128);
            gemm_tc<1, 2><<<grid, 256>>>(nullptr, 0, nullptr,
                                         (uint4*)(wtBase + WTO_SAW1 + l * 18864),
                                         sa_b1 + l * 131, sa_g1 + l * 131, sa_be1 + l * 131,
                                         (unsigned*)h1Pk, 144, rowsMax, 131, 144,
                                         featPk[l], posl[l], posl[l + 1], rmpL[l],
                                         n, m, drL[l]);
        }
        {
            dim3 grid(2, rowsMax / 128);
            gemm_tc<2, 1><<<grid, 256>>>(nullptr, 0, h1Pk,
                                         (uint4*)(wtBase + WTO_SAW2 + l * 18432),
                                         sa_b2 + l * 128, sa_g2 + l * 128, sa_be2 + l * 128,
                                         stgL[l], 128, rowsMax, 128, 144,
                                         nullptr, nullptr, nullptr, rmpL[l],
                                         n, m, drL[l]);
        }
        stage_to_pack<<<(nC * 64 + 255) / 256, 256>>>(stgL[l], nC, (unsigned*)featPk[l + 1]);
    }

    // ---- FP levels ----
    const uint4* cfeat = featPk[3];
    for (int step = 0; step < 3; step++) {
        int mi = 2 - step;
        int nc = nlev[mi + 1], nf = nlev[mi];
        fp_interp<<<NBATCH * (nf / 256), 256>>>(cfeat, posl[mi + 1], posl[mi],
                                                featPk[mi], nc, nf, finPk);
        int rows = NBATCH * nf;
        {
            dim3 grid(4, rows / 128);
            gemm_tc<1, 1><<<grid, 256>>>(nullptr, 0, finPk,
                                         (uint4*)(wtBase + WTO_FPW1 + mi * 65536),
                                         fp_b1 + mi * 256, fp_g1 + mi * 256, fp_be1 + mi * 256,
                                         (unsigned*)f1Pk, 256, rows, 256, 256,
                                         nullptr, nullptr, nullptr, nullptr, 0, 0, nullptr);
        }
        {
            dim3 grid(2, rows / 128);
            gemm_tc<1, 1><<<grid, 256>>>(nullptr, 0, f1Pk,
                                         (uint4*)(wtBase + WTO_FPW2 + mi * 32768),
                                         fp_b2 + mi * 128, fp_g2 + mi * 128, fp_be2 + mi * 128,
                                         (unsigned*)xfPk, 128, rows, 128, 256,
                                         nullptr, nullptr, nullptr, nullptr, 0, 0, nullptr);
        }
        cfeat = xfPk;
    }

    // ---- final MLP ----
    {
        dim3 grid(2, (NBATCH * 4096) / 128);
        gemm_tc<1, 1><<<grid, 256>>>(nullptr, 0, xfPk, (uint4*)(wtBase + WTO_LOW1),
                                     lo_b1, lo_g1, lo_be1,
                                     (unsigned*)f1Pk, 128, NBATCH * 4096, 128, 128,
                                     nullptr, nullptr, nullptr, nullptr, 0, 0, nullptr);
    }
    final_out<<<(NBATCH * 4096) / 32, 256>>>(f1Pk, lo_w2, lo_b2, lo_g2, lo_be2,
                                             out, NBATCH * 4096);
}